// round 12
// baseline (speedup 1.0000x reference)
#include <cuda_runtime.h>
#include <cuda_bf16.h>
#include <cuda_fp16.h>

#define L_SEQ   1024
#define DMODEL  2048
#define DINNER  4096
#define DSTATE  16
#define DTRANK  128
#define XPC     (DTRANK + 2 * DSTATE)   // 160
#define XPCP    256                     // padded GEMM2 N
#define TWOI    (2 * DINNER)
#define NCH     16              // scan chunks
#define CL      (L_SEQ / NCH)   // 64

// scratch (no allocation allowed)
__device__ __align__(16) __half g_xnc[L_SEQ * DMODEL];
__device__ __align__(16) __half g_w1c[TWOI * DMODEL];
__device__ __align__(16) __half g_uh[L_SEQ * DINNER];
__device__ __align__(16) __half g_wxph[XPCP * DINNER];
__device__ __align__(16) __half g_dtrh[L_SEQ * DTRANK];
__device__ __align__(16) __half g_wdth[DINNER * DTRANK];
__device__ __align__(16) __half g_yc[L_SEQ * DINNER];
__device__ __align__(16) __half g_w4c[DMODEL * DINNER];
__device__ float g_xz[L_SEQ * TWOI];
__device__ float g_u[L_SEQ * DINNER];
__device__ float g_xdbc[L_SEQ * XPC];
__device__ float g_delta[L_SEQ * DINNER];
#define G2_Z 8
__device__ float g_p2[G2_Z * L_SEQ * XPCP];
#define G4_Z 4
__device__ float g_p4[G4_Z * L_SEQ * DMODEL];
__device__ __align__(16) float g_hloc[NCH * DINNER * DSTATE];
__device__ __align__(16) float g_hin[NCH * DINNER * DSTATE];
__device__ float g_S[NCH * DINNER];

// ---------------- helpers ----------------
__device__ __forceinline__ unsigned smem_u32(const void* p) {
    unsigned a;
    asm("{ .reg .u64 t; cvta.to.shared.u64 t, %1; cvt.u32.u64 %0, t; }" : "=r"(a) : "l"(p));
    return a;
}
__device__ __forceinline__ void cpasync16(unsigned dst, const void* src) {
    asm volatile("cp.async.cg.shared.global [%0], [%1], 16;" :: "r"(dst), "l"(src) : "memory");
}
#define CP_COMMIT() asm volatile("cp.async.commit_group;" ::: "memory")
#define CP_WAIT1()  asm volatile("cp.async.wait_group 1;" ::: "memory")
__device__ __forceinline__ void ldsm_x4(unsigned& r0, unsigned& r1, unsigned& r2,
                                        unsigned& r3, unsigned addr) {
    asm volatile("ldmatrix.sync.aligned.m8n8.x4.shared.b16 {%0,%1,%2,%3}, [%4];"
                 : "=r"(r0), "=r"(r1), "=r"(r2), "=r"(r3) : "r"(addr));
}
__device__ __forceinline__ void mma16816(float* c, const unsigned* a, const unsigned* b) {
    asm volatile("mma.sync.aligned.m16n8k16.row.col.f32.f16.f16.f32 "
                 "{%0,%1,%2,%3}, {%4,%5,%6,%7}, {%8,%9}, {%0,%1,%2,%3};"
                 : "+f"(c[0]), "+f"(c[1]), "+f"(c[2]), "+f"(c[3])
                 : "r"(a[0]), "r"(a[1]), "r"(a[2]), "r"(a[3]), "r"(b[0]), "r"(b[1]));
}
// build p[n] = r^(n+1) for n=0..15 from r
__device__ __forceinline__ void pow_tree(float r, float* p) {
    p[0] = r; p[1] = r * r; p[2] = p[1] * r; p[3] = p[1] * p[1];
    const float r4 = p[3], r8 = r4 * r4, r12 = r8 * r4;
    #pragma unroll
    for (int j = 0; j < 4; j++) {
        p[4 + j] = p[j] * r4; p[8 + j] = p[j] * r8; p[12 + j] = p[j] * r12;
    }
}

// ------- weight transpose + convert: W[K,Nreal] fp32 -> Wc[Npad,K] fp16 -------
__global__ __launch_bounds__(256) void wconv_kernel(
    const float* __restrict__ W, __half* __restrict__ Wc, int K, int Nreal) {
    __shared__ float sW[32][33];
    const int n0 = blockIdx.x * 32, k0 = blockIdx.y * 32;
    const int c = threadIdx.x & 31, r = threadIdx.x >> 5;
    #pragma unroll
    for (int i = 0; i < 32; i += 8)
        sW[r + i][c] = (n0 + c < Nreal) ? W[(long)(k0 + r + i) * Nreal + n0 + c] : 0.f;
    __syncthreads();
    #pragma unroll
    for (int i = 0; i < 32; i += 8) {
        const int n = r + i;
        Wc[(long)(n0 + n) * K + k0 + c] = __float2half(sW[c][n]);
    }
}

// ---------------- RMSNorm -> xnc fp16 ----------------
__global__ __launch_bounds__(256) void rmsnorm_kernel(
    const float* __restrict__ x, const float* __restrict__ w,
    __half* __restrict__ xnc) {
    const int row = blockIdx.x;
    const float* xr = x + row * DMODEL;
    float s = 0.f;
    #pragma unroll
    for (int i = threadIdx.x; i < DMODEL; i += 256) {
        float v = xr[i];
        s += v * v;
    }
    #pragma unroll
    for (int o = 16; o > 0; o >>= 1) s += __shfl_xor_sync(0xffffffffu, s, o);
    __shared__ float red[8];
    __shared__ float rs_sh;
    if ((threadIdx.x & 31) == 0) red[threadIdx.x >> 5] = s;
    __syncthreads();
    if (threadIdx.x == 0) {
        float t = 0.f;
        #pragma unroll
        for (int i = 0; i < 8; i++) t += red[i];
        rs_sh = rsqrtf(t * (1.0f / DMODEL) + 1e-5f);
    }
    __syncthreads();
    const float rs = rs_sh;
    __half* dst = xnc + (long)row * DMODEL;
    #pragma unroll
    for (int i = threadIdx.x; i < DMODEL; i += 256)
        dst[i] = __float2half(xr[i] * rs * w[i]);
}

// ---------------- HMMA fp16 GEMM: 128x128 CTA, 4 warps of 64x64 ----------------
// A[M,ldk], B[N,ldk] fp16 K-major. BK=32, 3-stage cp.async, 128 threads,
// 2 CTAs/SM. Halves smem read traffic/MAC vs 8-warp 32x64 layout.
// EPI 0: plain store. EPI 1: softplus(acc + bias[col]).
#define MM_S 3
#define MM_OPBYTES (128 * 40 * 2)          // 10240
#define MM_STAGEB (2 * MM_OPBYTES)         // 20480
#define MM_SMEM (MM_S * MM_STAGEB)         // 61440

template <int EPI>
__global__ __launch_bounds__(128, 2) void gemm_mma_kernel(
    const __half* __restrict__ A, const __half* __restrict__ B,
    float* __restrict__ C, int ldk, int ktiles, int Ntot, long zstride,
    const float* __restrict__ bias) {
    extern __shared__ char smraw[];
    const unsigned sb = smem_u32(smraw);
    const int tid = threadIdx.x;
    const int wid = tid >> 5, lane = tid & 31;
    const int m0 = blockIdx.x * 128, n0 = blockIdx.y * 128;
    const long kz = (long)blockIdx.z * ktiles * 32;

    // loader: 128 threads, rows lr0+32j (j=0..3), 4 16B-chunks per row
    const int lr0 = tid >> 2;            // 0..31
    const int lch = tid & 3;             // 0..3
    const __half* Ag = A + (long)(m0 + lr0) * ldk + kz + lch * 8;
    const __half* Bg = B + (long)(n0 + lr0) * ldk + kz + lch * 8;
    const long rstep = 32L * ldk;
    const unsigned soff = lr0 * 80 + lch * 16;

    float acc[4][8][4];
    #pragma unroll
    for (int i = 0; i < 4; i++)
        #pragma unroll
        for (int j = 0; j < 8; j++)
            #pragma unroll
            for (int q = 0; q < 4; q++) acc[i][j][q] = 0.f;

    #pragma unroll
    for (int s = 0; s < MM_S - 1; s++) {
        const unsigned st = sb + s * MM_STAGEB;
        const long ko = (long)s * 32;
        #pragma unroll
        for (int j = 0; j < 4; j++) {
            cpasync16(st + soff + j * (32 * 80), Ag + j * rstep + ko);
            cpasync16(st + MM_OPBYTES + soff + j * (32 * 80), Bg + j * rstep + ko);
        }
        CP_COMMIT();
    }

    const int wm = (wid & 1) * 64;
    const int wn = (wid >> 1) * 64;
    const int lq = lane & 15;
    const int lh = (lane >> 4) * 16;

    int stage = 0, pstage = MM_S - 1;
    for (int kt = 0; kt < ktiles; kt++) {
        CP_WAIT1();
        __syncthreads();
        {
            const int pf = kt + MM_S - 1;
            if (pf < ktiles) {
                const unsigned st = sb + pstage * MM_STAGEB;
                const long ko = (long)pf * 32;
                #pragma unroll
                for (int j = 0; j < 4; j++) {
                    cpasync16(st + soff + j * (32 * 80), Ag + j * rstep + ko);
                    cpasync16(st + MM_OPBYTES + soff + j * (32 * 80), Bg + j * rstep + ko);
                }
            }
            CP_COMMIT();
            pstage = (pstage + 1 == MM_S) ? 0 : pstage + 1;
        }
        const unsigned sa = sb + stage * MM_STAGEB;
        const unsigned sbB = sa + MM_OPBYTES;
        stage = (stage + 1 == MM_S) ? 0 : stage + 1;
        #pragma unroll
        for (int ks = 0; ks < 2; ks++) {
            const int kc = ks * 32;
            unsigned af[4][4];
            #pragma unroll
            for (int mi = 0; mi < 4; mi++)
                ldsm_x4(af[mi][0], af[mi][1], af[mi][2], af[mi][3],
                        sa + (wm + mi * 16 + lq) * 80 + kc + lh);
            unsigned bf[8][2];
            #pragma unroll
            for (int nj = 0; nj < 4; nj++) {
                unsigned r0, r1, r2, r3;
                ldsm_x4(r0, r1, r2, r3, sbB + (wn + nj * 16 + lq) * 80 + kc + lh);
                bf[2 * nj][0] = r0; bf[2 * nj][1] = r2;
                bf[2 * nj + 1][0] = r1; bf[2 * nj + 1][1] = r3;
            }
            #pragma unroll
            for (int mi = 0; mi < 4; mi++)
                #pragma unroll
                for (int nt = 0; nt < 8; nt++)
                    mma16816(acc[mi][nt], af[mi], bf[nt]);
        }
    }

    float* Cb = C + (long)blockIdx.z * zstride;
    const int g = lane >> 2, t4 = lane & 3;
    #pragma unroll
    for (int mi = 0; mi < 4; mi++) {
        const int r0 = m0 + wm + mi * 16 + g;
        #pragma unroll
        for (int nt = 0; nt < 8; nt++) {
            const int c0 = n0 + wn + nt * 8 + t4 * 2;
            float2 v0 = make_float2(acc[mi][nt][0], acc[mi][nt][1]);
            float2 v1 = make_float2(acc[mi][nt][2], acc[mi][nt][3]);
            if (EPI == 1) {
                v0.x += bias[c0]; v0.y += bias[c0 + 1];
                v1.x += bias[c0]; v1.y += bias[c0 + 1];
                v0.x = (v0.x > 20.f) ? v0.x : log1pf(__expf(v0.x));
                v0.y = (v0.y > 20.f) ? v0.y : log1pf(__expf(v0.y));
                v1.x = (v1.x > 20.f) ? v1.x : log1pf(__expf(v1.x));
                v1.y = (v1.y > 20.f) ? v1.y : log1pf(__expf(v1.y));
            }
            *(float2*)&Cb[(long)r0 * Ntot + c0] = v0;
            *(float2*)&Cb[(long)(r0 + 8) * Ntot + c0] = v1;
        }
    }
}

// ---------------- reducers ----------------
__global__ __launch_bounds__(256) void reduce4_kernel(
    const float* __restrict__ p, const float* __restrict__ x, float* __restrict__ out) {
    const int idx = blockIdx.x * 256 + threadIdx.x;
    if (idx >= L_SEQ * DMODEL) return;
    const long off = (long)L_SEQ * DMODEL;
    out[idx] = x[idx] + ((p[idx] + p[idx + off]) + (p[idx + 2 * off] + p[idx + 3 * off]));
}

__global__ __launch_bounds__(256) void reduce2_kernel(
    const float* __restrict__ p, float* __restrict__ xdbc,
    __half* __restrict__ dtrh) {
    const int idx = blockIdx.x * 256 + threadIdx.x;
    if (idx >= L_SEQ * XPCP) return;
    const long off = (long)L_SEQ * XPCP;
    float s = 0.f;
    #pragma unroll
    for (int z = 0; z < G2_Z; z++) s += p[idx + z * off];
    const int l = idx >> 8;
    const int col = idx & (XPCP - 1);
    if (col < XPC) xdbc[(long)l * XPC + col] = s;
    if (col < DTRANK) dtrh[(long)l * DTRANK + col] = __float2half(s);
}

// ---------------- depthwise causal conv + SiLU -> u fp32 + uh fp16 ----------------
__global__ __launch_bounds__(256) void conv_silu_kernel(
    const float* __restrict__ xz, const float* __restrict__ cw,
    const float* __restrict__ cb, float* __restrict__ u,
    __half* __restrict__ uh) {
    const int idx = blockIdx.x * 256 + threadIdx.x;
    if (idx >= L_SEQ * DINNER) return;
    const int l = idx >> 12, d = idx & (DINNER - 1);
    float acc = cb[d];
    #pragma unroll
    for (int j = 0; j < 4; j++) {
        const int ll = l - 3 + j;
        if (ll >= 0) acc += xz[(long)ll * TWOI + d] * cw[j * DINNER + d];
    }
    const float v = acc / (1.f + __expf(-acc));
    u[idx] = v;
    uh[idx] = __float2half(v);
}

// ---------------- chunked parallel scan ----------------
__global__ __launch_bounds__(128) void scan_part1(
    const float* __restrict__ delta, const float* __restrict__ u,
    const float* __restrict__ xdbc, const float* __restrict__ A_log,
    float* __restrict__ hloc, float* __restrict__ S) {
    const int c = blockIdx.x;
    const int d = blockIdx.y * 128 + threadIdx.x;
    const int tid = threadIdx.x;
    const int l0 = c * CL;
    __shared__ float sB[CL][DSTATE];
    for (int t = tid; t < CL * DSTATE; t += 128) {
        const int i = t >> 4, n = t & 15;
        sB[i][n] = xdbc[(long)(l0 + i) * XPC + DTRANK + n];
    }
    float a[DSTATE];
    #pragma unroll
    for (int n = 0; n < DSTATE; n++) a[n] = -__expf(A_log[d * DSTATE + n]);
    const float a0 = a[0];
    bool pat = true;
    #pragma unroll
    for (int n = 1; n < DSTATE; n++) {
        const float e = a0 * (float)(n + 1);
        pat = pat && (fabsf(a[n] - e) <= 1e-4f * fabsf(e) + 1e-6f);
    }
    __syncthreads();
    float h[DSTATE];
    #pragma unroll
    for (int n = 0; n < DSTATE; n++) h[n] = 0.f;
    float Ss = 0.f;
    #pragma unroll 4
    for (int i = 0; i < CL; i++) {
        const int l = l0 + i;
        const float dl = delta[(long)l * DINNER + d];
        const float dbu = dl * u[(long)l * DINNER + d];
        Ss += dl;
        if (pat) {
            float p[DSTATE];
            pow_tree(__expf(dl * a0), p);
            #pragma unroll
            for (int n = 0; n < DSTATE; n++) h[n] = h[n] * p[n] + dbu * sB[i][n];
        } else {
            #pragma unroll
            for (int n = 0; n < DSTATE; n++)
                h[n] = h[n] * __expf(dl * a[n]) + dbu * sB[i][n];
        }
    }
    float4* dst = (float4*)(hloc + ((long)c * DINNER + d) * DSTATE);
    #pragma unroll
    for (int q = 0; q < 4; q++)
        dst[q] = make_float4(h[4 * q], h[4 * q + 1], h[4 * q + 2], h[4 * q + 3]);
    S[c * DINNER + d] = Ss;
}

__global__ __launch_bounds__(128) void scan_combine(
    const float* __restrict__ hloc, const float* __restrict__ S,
    const float* __restrict__ A_log, float* __restrict__ hin) {
    const int d = blockIdx.x * 128 + threadIdx.x;
    float a[DSTATE];
    #pragma unroll
    for (int n = 0; n < DSTATE; n++) a[n] = -__expf(A_log[d * DSTATE + n]);
    const float a0 = a[0];
    bool pat = true;
    #pragma unroll
    for (int n = 1; n < DSTATE; n++) {
        const float e = a0 * (float)(n + 1);
        pat = pat && (fabsf(a[n] - e) <= 1e-4f * fabsf(e) + 1e-6f);
    }
    float h[DSTATE];
    #pragma unroll
    for (int n = 0; n < DSTATE; n++) h[n] = 0.f;
    for (int c = 0; c < NCH; c++) {
        float4* dst = (float4*)(hin + ((long)c * DINNER + d) * DSTATE);
        #pragma unroll
        for (int q = 0; q < 4; q++)
            dst[q] = make_float4(h[4 * q], h[4 * q + 1], h[4 * q + 2], h[4 * q + 3]);
        const float Ss = S[c * DINNER + d];
        const float4* src = (const float4*)(hloc + ((long)c * DINNER + d) * DSTATE);
        float hl[DSTATE];
        #pragma unroll
        for (int q = 0; q < 4; q++) {
            float4 v = src[q];
            hl[4 * q] = v.x; hl[4 * q + 1] = v.y; hl[4 * q + 2] = v.z; hl[4 * q + 3] = v.w;
        }
        if (pat) {
            float p[DSTATE];
            pow_tree(__expf(Ss * a0), p);
            #pragma unroll
            for (int n = 0; n < DSTATE; n++) h[n] = h[n] * p[n] + hl[n];
        } else {
            #pragma unroll
            for (int n = 0; n < DSTATE; n++)
                h[n] = h[n] * __expf(Ss * a[n]) + hl[n];
        }
    }
}

__global__ __launch_bounds__(128) void scan_part2(
    const float* __restrict__ delta, const float* __restrict__ u,
    const float* __restrict__ xdbc, const float* __restrict__ A_log,
    const float* __restrict__ Dp, const float* __restrict__ xz,
    const float* __restrict__ hin, __half* __restrict__ yc) {
    const int c = blockIdx.x;
    const int d = blockIdx.y * 128 + threadIdx.x;
    const int tid = threadIdx.x;
    const int l0 = c * CL;
    __shared__ float sB[CL][DSTATE];
    __shared__ float sC[CL][DSTATE];
    for (int t = tid; t < CL * DSTATE; t += 128) {
        const int i = t >> 4, n = t & 15;
        sB[i][n] = xdbc[(long)(l0 + i) * XPC + DTRANK + n];
        sC[i][n] = xdbc[(long)(l0 + i) * XPC + DTRANK + DSTATE + n];
    }
    float a[DSTATE];
    #pragma unroll
    for (int n = 0; n < DSTATE; n++) a[n] = -__expf(A_log[d * DSTATE + n]);
    const float a0 = a[0];
    bool pat = true;
    #pragma unroll
    for (int n = 1; n < DSTATE; n++) {
        const float e = a0 * (float)(n + 1);
        pat = pat && (fabsf(a[n] - e) <= 1e-4f * fabsf(e) + 1e-6f);
    }
    const float Dd = Dp[d];
    float h[DSTATE];
    {
        const float4* src = (const float4*)(hin + ((long)c * DINNER + d) * DSTATE);
        #pragma unroll
        for (int q = 0; q < 4; q++) {
            float4 v = src[q];
            h[4 * q] = v.x; h[4 * q + 1] = v.y; h[4 * q + 2] = v.z; h[4 * q + 3] = v.w;
        }
    }
    __syncthreads();
    #pragma unroll 4
    for (int i = 0; i < CL; i++) {
        const int l = l0 + i;
        const float dl = delta[(long)l * DINNER + d];
        const float uv = u[(long)l * DINNER + d];
        const float dbu = dl * uv;
        if (pat) {
            float p[DSTATE];
            pow_tree(__expf(dl * a0), p);
            #pragma unroll
            for (int n = 0; n < DSTATE; n++) h[n] = h[n] * p[n] + dbu * sB[i][n];
        } else {
            #pragma unroll
            for (int n = 0; n < DSTATE; n++)
                h[n] = h[n] * __expf(dl * a[n]) + dbu * sB[i][n];
        }
        float y0 = 0.f, y1 = 0.f, y2 = 0.f, y3 = 0.f;
        #pragma unroll
        for (int n = 0; n < DSTATE; n += 4) {
            y0 += h[n] * sC[i][n]; y1 += h[n + 1] * sC[i][n + 1];
            y2 += h[n + 2] * sC[i][n + 2]; y3 += h[n + 3] * sC[i][n + 3];
        }
        const float res = xz[(long)l * TWOI + DINNER + d];
        const float val = ((y0 + y1) + (y2 + y3) + uv * Dd) * (res / (1.f + __expf(-res)));
        yc[(long)l * DINNER + d] = __float2half(val);
    }
}

// ---------------- launch ----------------
extern "C" void kernel_launch(void* const* d_in, const int* in_sizes, int n_in,
                              void* d_out, int out_size) {
    const float* x      = (const float*)d_in[0];
    const float* w_norm = (const float*)d_in[1];
    const float* W_in   = (const float*)d_in[2];
    const float* conv_w = (const float*)d_in[3];
    const float* conv_b = (const float*)d_in[4];
    const float* W_xp   = (const float*)d_in[5];
    const float* W_dt   = (const float*)d_in[6];
    const float* b_dt   = (const float*)d_in[7];
    const float* A_log  = (const float*)d_in[8];
    const float* Dp     = (const float*)d_in[9];
    const float* W_out  = (const float*)d_in[10];
    float* out = (float*)d_out;

    __half *xnc, *w1c, *uh, *wxph, *dtrh, *wdth, *yc, *w4c;
    float *xz, *u, *xdbc, *delta, *p2, *p4, *hloc, *hin, *S;
    cudaGetSymbolAddress((void**)&xnc, g_xnc);
    cudaGetSymbolAddress((void**)&w1c, g_w1c);
    cudaGetSymbolAddress((void**)&uh, g_uh);
    cudaGetSymbolAddress((void**)&wxph, g_wxph);
    cudaGetSymbolAddress((void**)&dtrh, g_dtrh);
    cudaGetSymbolAddress((void**)&wdth, g_wdth);
    cudaGetSymbolAddress((void**)&yc, g_yc);
    cudaGetSymbolAddress((void**)&w4c, g_w4c);
    cudaGetSymbolAddress((void**)&xz, g_xz);
    cudaGetSymbolAddress((void**)&u, g_u);
    cudaGetSymbolAddress((void**)&xdbc, g_xdbc);
    cudaGetSymbolAddress((void**)&delta, g_delta);
    cudaGetSymbolAddress((void**)&p2, g_p2);
    cudaGetSymbolAddress((void**)&p4, g_p4);
    cudaGetSymbolAddress((void**)&hloc, g_hloc);
    cudaGetSymbolAddress((void**)&hin, g_hin);
    cudaGetSymbolAddress((void**)&S, g_S);

    cudaFuncSetAttribute(gemm_mma_kernel<0>,
                         cudaFuncAttributeMaxDynamicSharedMemorySize, MM_SMEM);
    cudaFuncSetAttribute(gemm_mma_kernel<1>,
                         cudaFuncAttributeMaxDynamicSharedMemorySize, MM_SMEM);

    // weight transpose + fp16 convert
    wconv_kernel<<<dim3(TWOI / 32, DMODEL / 32), 256>>>(W_in, w1c, DMODEL, TWOI);
    wconv_kernel<<<dim3(DMODEL / 32, DINNER / 32), 256>>>(W_out, w4c, DINNER, DMODEL);
    wconv_kernel<<<dim3(XPCP / 32, DINNER / 32), 256>>>(W_xp, wxph, DINNER, XPC);
    wconv_kernel<<<dim3(DINNER / 32, DTRANK / 32), 256>>>(W_dt, wdth, DTRANK, DINNER);

    rmsnorm_kernel<<<L_SEQ, 256>>>(x, w_norm, xnc);

    // GEMM1: xz = xn @ W_in  (fp16 HMMA, K=2048)
    gemm_mma_kernel<0><<<dim3(L_SEQ / 128, TWOI / 128, 1), 128, MM_SMEM>>>(
        xnc, w1c, xz, DMODEL, DMODEL / 32, TWOI, 0, nullptr);

    conv_silu_kernel<<<(L_SEQ * DINNER) / 256, 256>>>(xz, conv_w, conv_b, u, uh);

    // GEMM2: xdbc = u @ W_xp  (fp16 HMMA, N padded 256, split-K z=8)
    gemm_mma_kernel<0><<<dim3(L_SEQ / 128, XPCP / 128, G2_Z), 128, MM_SMEM>>>(
        uh, wxph, p2, DINNER, DINNER / 32 / G2_Z, XPCP, (long)L_SEQ * XPCP, nullptr);
    reduce2_kernel<<<(L_SEQ * XPCP + 255) / 256, 256>>>(p2, xdbc, dtrh);

    // GEMM3: delta = softplus(dt_r @ W_dt + b_dt)  (fp16 HMMA, K=128)
    gemm_mma_kernel<1><<<dim3(L_SEQ / 128, DINNER / 128, 1), 128, MM_SMEM>>>(
        dtrh, wdth, delta, DTRANK, DTRANK / 32, DINNER, 0, b_dt);

    // chunked scan (NCH=16)
    scan_part1<<<dim3(NCH, DINNER / 128), 128>>>(delta, u, xdbc, A_log, hloc, S);
    scan_combine<<<DINNER / 128, 128>>>(hloc, S, A_log, hin);
    scan_part2<<<dim3(NCH, DINNER / 128), 128>>>(delta, u, xdbc, A_log, Dp, xz, hin, yc);

    // GEMM4: p4[z] = (yz @ W_out) split-K z=4  (fp16 HMMA, K=4096)
    gemm_mma_kernel<0><<<dim3(L_SEQ / 128, DMODEL / 128, G4_Z), 128, MM_SMEM>>>(
        yc, w4c, p4, DINNER, DINNER / 32 / G4_Z, DMODEL, (long)L_SEQ * DMODEL, nullptr);

    reduce4_kernel<<<(L_SEQ * DMODEL + 255) / 256, 256>>>(p4, x, out);
}

// round 13
// speedup vs baseline: 1.0477x; 1.0477x over previous
#include <cuda_runtime.h>
#include <cuda_bf16.h>
#include <cuda_fp16.h>

#define L_SEQ   1024
#define DMODEL  2048
#define DINNER  4096
#define DSTATE  16
#define DTRANK  128
#define XPC     (DTRANK + 2 * DSTATE)   // 160
#define XPCP    256                     // padded GEMM2 N
#define TWOI    (2 * DINNER)
#define NCH     16              // scan chunks
#define CL      (L_SEQ / NCH)   // 64

// scratch (no allocation allowed)
__device__ __align__(16) __half g_xnc[L_SEQ * DMODEL];
__device__ __align__(16) __half g_w1c[TWOI * DMODEL];
__device__ __align__(16) __half g_uh[L_SEQ * DINNER];
__device__ __align__(16) __half g_wxph[XPCP * DINNER];
__device__ __align__(16) __half g_dtrh[L_SEQ * DTRANK];
__device__ __align__(16) __half g_wdth[DINNER * DTRANK];
__device__ __align__(16) __half g_yc[L_SEQ * DINNER];
__device__ __align__(16) __half g_w4c[DMODEL * DINNER];
__device__ float g_xz[L_SEQ * TWOI];
__device__ float g_xdbc[L_SEQ * XPC];
__device__ float g_delta[L_SEQ * DINNER];
__device__ float g_rc[L_SEQ * DINNER];      // cached exp(delta*a0)
#define G2_Z 16
__device__ float g_p2[G2_Z * L_SEQ * XPCP];
#define G4_Z 4
__device__ float g_p4[G4_Z * L_SEQ * DMODEL];
__device__ __align__(16) float g_hloc[NCH * DINNER * DSTATE];
__device__ __align__(16) float g_hin[NCH * DINNER * DSTATE];
__device__ float g_S[NCH * DINNER];

// ---------------- helpers ----------------
__device__ __forceinline__ unsigned smem_u32(const void* p) {
    unsigned a;
    asm("{ .reg .u64 t; cvta.to.shared.u64 t, %1; cvt.u32.u64 %0, t; }" : "=r"(a) : "l"(p));
    return a;
}
__device__ __forceinline__ void cpasync16(unsigned dst, const void* src) {
    asm volatile("cp.async.cg.shared.global [%0], [%1], 16;" :: "r"(dst), "l"(src) : "memory");
}
#define CP_COMMIT() asm volatile("cp.async.commit_group;" ::: "memory")
#define CP_WAIT1()  asm volatile("cp.async.wait_group 1;" ::: "memory")
__device__ __forceinline__ void ldsm_x4(unsigned& r0, unsigned& r1, unsigned& r2,
                                        unsigned& r3, unsigned addr) {
    asm volatile("ldmatrix.sync.aligned.m8n8.x4.shared.b16 {%0,%1,%2,%3}, [%4];"
                 : "=r"(r0), "=r"(r1), "=r"(r2), "=r"(r3) : "r"(addr));
}
__device__ __forceinline__ void mma16816(float* c, const unsigned* a, const unsigned* b) {
    asm volatile("mma.sync.aligned.m16n8k16.row.col.f32.f16.f16.f32 "
                 "{%0,%1,%2,%3}, {%4,%5,%6,%7}, {%8,%9}, {%0,%1,%2,%3};"
                 : "+f"(c[0]), "+f"(c[1]), "+f"(c[2]), "+f"(c[3])
                 : "r"(a[0]), "r"(a[1]), "r"(a[2]), "r"(a[3]), "r"(b[0]), "r"(b[1]));
}
// build p[n] = r^(n+1) for n=0..15 from r
__device__ __forceinline__ void pow_tree(float r, float* p) {
    p[0] = r; p[1] = r * r; p[2] = p[1] * r; p[3] = p[1] * p[1];
    const float r4 = p[3], r8 = r4 * r4, r12 = r8 * r4;
    #pragma unroll
    for (int j = 0; j < 4; j++) {
        p[4 + j] = p[j] * r4; p[8 + j] = p[j] * r8; p[12 + j] = p[j] * r12;
    }
}

// ------- weight transpose + convert: W[K,Nreal] fp32 -> Wc[Npad,K] fp16 -------
__global__ __launch_bounds__(256) void wconv_kernel(
    const float* __restrict__ W, __half* __restrict__ Wc, int K, int Nreal) {
    __shared__ float sW[32][33];
    const int n0 = blockIdx.x * 32, k0 = blockIdx.y * 32;
    const int c = threadIdx.x & 31, r = threadIdx.x >> 5;
    #pragma unroll
    for (int i = 0; i < 32; i += 8)
        sW[r + i][c] = (n0 + c < Nreal) ? W[(long)(k0 + r + i) * Nreal + n0 + c] : 0.f;
    __syncthreads();
    #pragma unroll
    for (int i = 0; i < 32; i += 8) {
        const int n = r + i;
        Wc[(long)(n0 + n) * K + k0 + c] = __float2half(sW[c][n]);
    }
}

// ---------------- RMSNorm -> xnc fp16 ----------------
__global__ __launch_bounds__(256) void rmsnorm_kernel(
    const float* __restrict__ x, const float* __restrict__ w,
    __half* __restrict__ xnc) {
    const int row = blockIdx.x;
    const float* xr = x + row * DMODEL;
    float s = 0.f;
    #pragma unroll
    for (int i = threadIdx.x; i < DMODEL; i += 256) {
        float v = xr[i];
        s += v * v;
    }
    #pragma unroll
    for (int o = 16; o > 0; o >>= 1) s += __shfl_xor_sync(0xffffffffu, s, o);
    __shared__ float red[8];
    __shared__ float rs_sh;
    if ((threadIdx.x & 31) == 0) red[threadIdx.x >> 5] = s;
    __syncthreads();
    if (threadIdx.x == 0) {
        float t = 0.f;
        #pragma unroll
        for (int i = 0; i < 8; i++) t += red[i];
        rs_sh = rsqrtf(t * (1.0f / DMODEL) + 1e-5f);
    }
    __syncthreads();
    const float rs = rs_sh;
    __half* dst = xnc + (long)row * DMODEL;
    #pragma unroll
    for (int i = threadIdx.x; i < DMODEL; i += 256)
        dst[i] = __float2half(xr[i] * rs * w[i]);
}

// ---------------- HMMA fp16 GEMM (R11 core: 128x128 CTA, 8 warps 32x64) --------
#define MM_S 3
#define MM_OPBYTES (128 * 40 * 2)          // 10240
#define MM_STAGEB (2 * MM_OPBYTES)         // 20480
#define MM_SMEM (MM_S * MM_STAGEB)         // 61440

template <int EPI>
__global__ __launch_bounds__(256, 2) void gemm_mma_kernel(
    const __half* __restrict__ A, const __half* __restrict__ B,
    float* __restrict__ C, int ldk, int ktiles, int Ntot, long zstride,
    const float* __restrict__ bias) {
    extern __shared__ char smraw[];
    const unsigned sb = smem_u32(smraw);
    const int tid = threadIdx.x;
    const int wid = tid >> 5, lane = tid & 31;
    const int m0 = blockIdx.x * 128, n0 = blockIdx.y * 128;
    const long kz = (long)blockIdx.z * ktiles * 32;

    const int lrow = tid >> 2;
    const int lch = tid & 3;
    const __half* Ag = A + (long)(m0 + lrow) * ldk + kz + lch * 8;
    const __half* Bg = B + (long)(n0 + lrow) * ldk + kz + lch * 8;
    const long half64 = 64L * ldk;
    const unsigned soff = lrow * 80 + lch * 16;

    float acc[2][8][4];
    #pragma unroll
    for (int i = 0; i < 2; i++)
        #pragma unroll
        for (int j = 0; j < 8; j++)
            #pragma unroll
            for (int q = 0; q < 4; q++) acc[i][j][q] = 0.f;

    #pragma unroll
    for (int s = 0; s < MM_S - 1; s++) {
        const unsigned st = sb + s * MM_STAGEB;
        const long ko = (long)s * 32;
        cpasync16(st + soff, Ag + ko);
        cpasync16(st + soff + 64 * 80, Ag + half64 + ko);
        cpasync16(st + MM_OPBYTES + soff, Bg + ko);
        cpasync16(st + MM_OPBYTES + soff + 64 * 80, Bg + half64 + ko);
        CP_COMMIT();
    }

    const int wm = (wid & 3) * 32;
    const int wn = (wid >> 2) * 64;
    const int lq = lane & 15;
    const int lh = (lane >> 4) * 16;

    int stage = 0, pstage = MM_S - 1;
    for (int kt = 0; kt < ktiles; kt++) {
        CP_WAIT1();
        __syncthreads();
        {
            const int pf = kt + MM_S - 1;
            if (pf < ktiles) {
                const unsigned st = sb + pstage * MM_STAGEB;
                const long ko = (long)pf * 32;
                cpasync16(st + soff, Ag + ko);
                cpasync16(st + soff + 64 * 80, Ag + half64 + ko);
                cpasync16(st + MM_OPBYTES + soff, Bg + ko);
                cpasync16(st + MM_OPBYTES + soff + 64 * 80, Bg + half64 + ko);
            }
            CP_COMMIT();
            pstage = (pstage + 1 == MM_S) ? 0 : pstage + 1;
        }
        const unsigned sa = sb + stage * MM_STAGEB;
        const unsigned sbB = sa + MM_OPBYTES;
        stage = (stage + 1 == MM_S) ? 0 : stage + 1;
        #pragma unroll
        for (int ks = 0; ks < 2; ks++) {
            const int kc = ks * 32;
            unsigned af[2][4];
            #pragma unroll
            for (int mi = 0; mi < 2; mi++)
                ldsm_x4(af[mi][0], af[mi][1], af[mi][2], af[mi][3],
                        sa + (wm + mi * 16 + lq) * 80 + kc + lh);
            unsigned bf[8][2];
            #pragma unroll
            for (int nj = 0; nj < 4; nj++) {
                unsigned r0, r1, r2, r3;
                ldsm_x4(r0, r1, r2, r3, sbB + (wn + nj * 16 + lq) * 80 + kc + lh);
                bf[2 * nj][0] = r0; bf[2 * nj][1] = r2;
                bf[2 * nj + 1][0] = r1; bf[2 * nj + 1][1] = r3;
            }
            #pragma unroll
            for (int mi = 0; mi < 2; mi++)
                #pragma unroll
                for (int nt = 0; nt < 8; nt++)
                    mma16816(acc[mi][nt], af[mi], bf[nt]);
        }
    }

    float* Cb = C + (long)blockIdx.z * zstride;
    const int g = lane >> 2, t4 = lane & 3;
    #pragma unroll
    for (int mi = 0; mi < 2; mi++) {
        const int r0 = m0 + wm + mi * 16 + g;
        #pragma unroll
        for (int nt = 0; nt < 8; nt++) {
            const int c0 = n0 + wn + nt * 8 + t4 * 2;
            float2 v0 = make_float2(acc[mi][nt][0], acc[mi][nt][1]);
            float2 v1 = make_float2(acc[mi][nt][2], acc[mi][nt][3]);
            if (EPI == 1) {
                v0.x += bias[c0]; v0.y += bias[c0 + 1];
                v1.x += bias[c0]; v1.y += bias[c0 + 1];
                v0.x = (v0.x > 20.f) ? v0.x : log1pf(__expf(v0.x));
                v0.y = (v0.y > 20.f) ? v0.y : log1pf(__expf(v0.y));
                v1.x = (v1.x > 20.f) ? v1.x : log1pf(__expf(v1.x));
                v1.y = (v1.y > 20.f) ? v1.y : log1pf(__expf(v1.y));
            }
            *(float2*)&Cb[(long)r0 * Ntot + c0] = v0;
            *(float2*)&Cb[(long)(r0 + 8) * Ntot + c0] = v1;
        }
    }
}

// ---------------- reducers ----------------
__global__ __launch_bounds__(256) void reduce4_kernel(
    const float* __restrict__ p, const float* __restrict__ x, float* __restrict__ out) {
    const int idx = blockIdx.x * 256 + threadIdx.x;
    if (idx >= L_SEQ * DMODEL) return;
    const long off = (long)L_SEQ * DMODEL;
    out[idx] = x[idx] + ((p[idx] + p[idx + off]) + (p[idx + 2 * off] + p[idx + 3 * off]));
}

__global__ __launch_bounds__(256) void reduce2_kernel(
    const float* __restrict__ p, float* __restrict__ xdbc,
    __half* __restrict__ dtrh) {
    const int idx = blockIdx.x * 256 + threadIdx.x;
    if (idx >= L_SEQ * XPCP) return;
    const long off = (long)L_SEQ * XPCP;
    float s = 0.f;
    #pragma unroll
    for (int z = 0; z < G2_Z; z++) s += p[idx + z * off];
    const int l = idx >> 8;
    const int col = idx & (XPCP - 1);
    if (col < XPC) xdbc[(long)l * XPC + col] = s;
    if (col < DTRANK) dtrh[(long)l * DTRANK + col] = __float2half(s);
}

// ---------------- depthwise causal conv + SiLU -> uh fp16 only ----------------
__global__ __launch_bounds__(256) void conv_silu_kernel(
    const float* __restrict__ xz, const float* __restrict__ cw,
    const float* __restrict__ cb, __half* __restrict__ uh) {
    const int idx = blockIdx.x * 256 + threadIdx.x;
    if (idx >= L_SEQ * DINNER) return;
    const int l = idx >> 12, d = idx & (DINNER - 1);
    float acc = cb[d];
    #pragma unroll
    for (int j = 0; j < 4; j++) {
        const int ll = l - 3 + j;
        if (ll >= 0) acc += xz[(long)ll * TWOI + d] * cw[j * DINNER + d];
    }
    const float v = acc / (1.f + __expf(-acc));
    uh[idx] = __float2half(v);
}

// ---------------- chunked parallel scan ----------------
__global__ __launch_bounds__(128) void scan_part1(
    const float* __restrict__ delta, const __half* __restrict__ uh,
    const float* __restrict__ xdbc, const float* __restrict__ A_log,
    float* __restrict__ hloc, float* __restrict__ S, float* __restrict__ rc) {
    const int c = blockIdx.x;
    const int d = blockIdx.y * 128 + threadIdx.x;
    const int tid = threadIdx.x;
    const int l0 = c * CL;
    __shared__ float sB[CL][DSTATE];
    for (int t = tid; t < CL * DSTATE; t += 128) {
        const int i = t >> 4, n = t & 15;
        sB[i][n] = xdbc[(long)(l0 + i) * XPC + DTRANK + n];
    }
    float a[DSTATE];
    #pragma unroll
    for (int n = 0; n < DSTATE; n++) a[n] = -__expf(A_log[d * DSTATE + n]);
    const float a0 = a[0];
    bool pat = true;
    #pragma unroll
    for (int n = 1; n < DSTATE; n++) {
        const float e = a0 * (float)(n + 1);
        pat = pat && (fabsf(a[n] - e) <= 1e-4f * fabsf(e) + 1e-6f);
    }
    __syncthreads();
    float h[DSTATE];
    #pragma unroll
    for (int n = 0; n < DSTATE; n++) h[n] = 0.f;
    float Ss = 0.f;
    #pragma unroll 4
    for (int i = 0; i < CL; i++) {
        const int l = l0 + i;
        const float dl = delta[(long)l * DINNER + d];
        const float dbu = dl * __half2float(uh[(long)l * DINNER + d]);
        Ss += dl;
        if (pat) {
            const float r = __expf(dl * a0);
            rc[(long)l * DINNER + d] = r;
            float p[DSTATE];
            pow_tree(r, p);
            #pragma unroll
            for (int n = 0; n < DSTATE; n++) h[n] = h[n] * p[n] + dbu * sB[i][n];
        } else {
            #pragma unroll
            for (int n = 0; n < DSTATE; n++)
                h[n] = h[n] * __expf(dl * a[n]) + dbu * sB[i][n];
        }
    }
    float4* dst = (float4*)(hloc + ((long)c * DINNER + d) * DSTATE);
    #pragma unroll
    for (int q = 0; q < 4; q++)
        dst[q] = make_float4(h[4 * q], h[4 * q + 1], h[4 * q + 2], h[4 * q + 3]);
    S[c * DINNER + d] = Ss;
}

__global__ __launch_bounds__(128) void scan_combine(
    const float* __restrict__ hloc, const float* __restrict__ S,
    const float* __restrict__ A_log, float* __restrict__ hin) {
    const int d = blockIdx.x * 128 + threadIdx.x;
    float a[DSTATE];
    #pragma unroll
    for (int n = 0; n < DSTATE; n++) a[n] = -__expf(A_log[d * DSTATE + n]);
    const float a0 = a[0];
    bool pat = true;
    #pragma unroll
    for (int n = 1; n < DSTATE; n++) {
        const float e = a0 * (float)(n + 1);
        pat = pat && (fabsf(a[n] - e) <= 1e-4f * fabsf(e) + 1e-6f);
    }
    float h[DSTATE];
    #pragma unroll
    for (int n = 0; n < DSTATE; n++) h[n] = 0.f;
    for (int c = 0; c < NCH; c++) {
        float4* dst = (float4*)(hin + ((long)c * DINNER + d) * DSTATE);
        #pragma unroll
        for (int q = 0; q < 4; q++)
            dst[q] = make_float4(h[4 * q], h[4 * q + 1], h[4 * q + 2], h[4 * q + 3]);
        const float Ss = S[c * DINNER + d];
        const float4* src = (const float4*)(hloc + ((long)c * DINNER + d) * DSTATE);
        float hl[DSTATE];
        #pragma unroll
        for (int q = 0; q < 4; q++) {
            float4 v = src[q];
            hl[4 * q] = v.x; hl[4 * q + 1] = v.y; hl[4 * q + 2] = v.z; hl[4 * q + 3] = v.w;
        }
        if (pat) {
            float p[DSTATE];
            pow_tree(__expf(Ss * a0), p);
            #pragma unroll
            for (int n = 0; n < DSTATE; n++) h[n] = h[n] * p[n] + hl[n];
        } else {
            #pragma unroll
            for (int n = 0; n < DSTATE; n++)
                h[n] = h[n] * __expf(Ss * a[n]) + hl[n];
        }
    }
}

__global__ __launch_bounds__(128) void scan_part2(
    const float* __restrict__ delta, const __half* __restrict__ uh,
    const float* __restrict__ xdbc, const float* __restrict__ A_log,
    const float* __restrict__ Dp, const float* __restrict__ xz,
    const float* __restrict__ hin, const float* __restrict__ rc,
    __half* __restrict__ yc) {
    const int c = blockIdx.x;
    const int d = blockIdx.y * 128 + threadIdx.x;
    const int tid = threadIdx.x;
    const int l0 = c * CL;
    __shared__ float sB[CL][DSTATE];
    __shared__ float sC[CL][DSTATE];
    for (int t = tid; t < CL * DSTATE; t += 128) {
        const int i = t >> 4, n = t & 15;
        sB[i][n] = xdbc[(long)(l0 + i) * XPC + DTRANK + n];
        sC[i][n] = xdbc[(long)(l0 + i) * XPC + DTRANK + DSTATE + n];
    }
    float a[DSTATE];
    #pragma unroll
    for (int n = 0; n < DSTATE; n++) a[n] = -__expf(A_log[d * DSTATE + n]);
    const float a0 = a[0];
    bool pat = true;
    #pragma unroll
    for (int n = 1; n < DSTATE; n++) {
        const float e = a0 * (float)(n + 1);
        pat = pat && (fabsf(a[n] - e) <= 1e-4f * fabsf(e) + 1e-6f);
    }
    const float Dd = Dp[d];
    float h[DSTATE];
    {
        const float4* src = (const float4*)(hin + ((long)c * DINNER + d) * DSTATE);
        #pragma unroll
        for (int q = 0; q < 4; q++) {
            float4 v = src[q];
            h[4 * q] = v.x; h[4 * q + 1] = v.y; h[4 * q + 2] = v.z; h[4 * q + 3] = v.w;
        }
    }
    __syncthreads();
    #pragma unroll 4
    for (int i = 0; i < CL; i++) {
        const int l = l0 + i;
        const float dl = delta[(long)l * DINNER + d];
        const float uv = __half2float(uh[(long)l * DINNER + d]);
        const float dbu = dl * uv;
        if (pat) {
            float p[DSTATE];
            pow_tree(rc[(long)l * DINNER + d], p);
            #pragma unroll
            for (int n = 0; n < DSTATE; n++) h[n] = h[n] * p[n] + dbu * sB[i][n];
        } else {
            #pragma unroll
            for (int n = 0; n < DSTATE; n++)
                h[n] = h[n] * __expf(dl * a[n]) + dbu * sB[i][n];
        }
        float y0 = 0.f, y1 = 0.f, y2 = 0.f, y3 = 0.f;
        #pragma unroll
        for (int n = 0; n < DSTATE; n += 4) {
            y0 += h[n] * sC[i][n]; y1 += h[n + 1] * sC[i][n + 1];
            y2 += h[n + 2] * sC[i][n + 2]; y3 += h[n + 3] * sC[i][n + 3];
        }
        const float res = xz[(long)l * TWOI + DINNER + d];
        const float val = ((y0 + y1) + (y2 + y3) + uv * Dd) * (res / (1.f + __expf(-res)));
        yc[(long)l * DINNER + d] = __float2half(val);
    }
}

// ---------------- launch ----------------
extern "C" void kernel_launch(void* const* d_in, const int* in_sizes, int n_in,
                              void* d_out, int out_size) {
    const float* x      = (const float*)d_in[0];
    const float* w_norm = (const float*)d_in[1];
    const float* W_in   = (const float*)d_in[2];
    const float* conv_w = (const float*)d_in[3];
    const float* conv_b = (const float*)d_in[4];
    const float* W_xp   = (const float*)d_in[5];
    const float* W_dt   = (const float*)d_in[6];
    const float* b_dt   = (const float*)d_in[7];
    const float* A_log  = (const float*)d_in[8];
    const float* Dp     = (const float*)d_in[9];
    const float* W_out  = (const float*)d_in[10];
    float* out = (float*)d_out;

    __half *xnc, *w1c, *uh, *wxph, *dtrh, *wdth, *yc, *w4c;
    float *xz, *xdbc, *delta, *rcp, *p2, *p4, *hloc, *hin, *S;
    cudaGetSymbolAddress((void**)&xnc, g_xnc);
    cudaGetSymbolAddress((void**)&w1c, g_w1c);
    cudaGetSymbolAddress((void**)&uh, g_uh);
    cudaGetSymbolAddress((void**)&wxph, g_wxph);
    cudaGetSymbolAddress((void**)&dtrh, g_dtrh);
    cudaGetSymbolAddress((void**)&wdth, g_wdth);
    cudaGetSymbolAddress((void**)&yc, g_yc);
    cudaGetSymbolAddress((void**)&w4c, g_w4c);
    cudaGetSymbolAddress((void**)&xz, g_xz);
    cudaGetSymbolAddress((void**)&xdbc, g_xdbc);
    cudaGetSymbolAddress((void**)&delta, g_delta);
    cudaGetSymbolAddress((void**)&rcp, g_rc);
    cudaGetSymbolAddress((void**)&p2, g_p2);
    cudaGetSymbolAddress((void**)&p4, g_p4);
    cudaGetSymbolAddress((void**)&hloc, g_hloc);
    cudaGetSymbolAddress((void**)&hin, g_hin);
    cudaGetSymbolAddress((void**)&S, g_S);

    cudaFuncSetAttribute(gemm_mma_kernel<0>,
                         cudaFuncAttributeMaxDynamicSharedMemorySize, MM_SMEM);
    cudaFuncSetAttribute(gemm_mma_kernel<1>,
                         cudaFuncAttributeMaxDynamicSharedMemorySize, MM_SMEM);

    // weight transpose + fp16 convert
    wconv_kernel<<<dim3(TWOI / 32, DMODEL / 32), 256>>>(W_in, w1c, DMODEL, TWOI);
    wconv_kernel<<<dim3(DMODEL / 32, DINNER / 32), 256>>>(W_out, w4c, DINNER, DMODEL);
    wconv_kernel<<<dim3(XPCP / 32, DINNER / 32), 256>>>(W_xp, wxph, DINNER, XPC);
    wconv_kernel<<<dim3(DINNER / 32, DTRANK / 32), 256>>>(W_dt, wdth, DTRANK, DINNER);

    rmsnorm_kernel<<<L_SEQ, 256>>>(x, w_norm, xnc);

    // GEMM1: xz = xn @ W_in  (fp16 HMMA, K=2048)
    gemm_mma_kernel<0><<<dim3(L_SEQ / 128, TWOI / 128, 1), 256, MM_SMEM>>>(
        xnc, w1c, xz, DMODEL, DMODEL / 32, TWOI, 0, nullptr);

    conv_silu_kernel<<<(L_SEQ * DINNER) / 256, 256>>>(xz, conv_w, conv_b, uh);

    // GEMM2: xdbc = u @ W_xp  (fp16 HMMA, N padded 256, split-K z=16)
    gemm_mma_kernel<0><<<dim3(L_SEQ / 128, XPCP / 128, G2_Z), 256, MM_SMEM>>>(
        uh, wxph, p2, DINNER, DINNER / 32 / G2_Z, XPCP, (long)L_SEQ * XPCP, nullptr);
    reduce2_kernel<<<(L_SEQ * XPCP + 255) / 256, 256>>>(p2, xdbc, dtrh);

    // GEMM3: delta = softplus(dt_r @ W_dt + b_dt)  (fp16 HMMA, K=128)
    gemm_mma_kernel<1><<<dim3(L_SEQ / 128, DINNER / 128, 1), 256, MM_SMEM>>>(
        dtrh, wdth, delta, DTRANK, DTRANK / 32, DINNER, 0, b_dt);

    // chunked scan (NCH=16)
    scan_part1<<<dim3(NCH, DINNER / 128), 128>>>(delta, uh, xdbc, A_log, hloc, S, rcp);
    scan_combine<<<DINNER / 128, 128>>>(hloc, S, A_log, hin);
    scan_part2<<<dim3(NCH, DINNER / 128), 128>>>(delta, uh, xdbc, A_log, Dp, xz, hin, rcp, yc);

    // GEMM4: p4[z] = (yz @ W_out) split-K z=4  (fp16 HMMA, K=4096)
    gemm_mma_kernel<0><<<dim3(L_SEQ / 128, DMODEL / 128, G4_Z), 256, MM_SMEM>>>(
        yc, w4c, p4, DINNER, DINNER / 32 / G4_Z, DMODEL, (long)L_SEQ * DMODEL, nullptr);

    reduce4_kernel<<<(L_SEQ * DMODEL + 255) / 256, 256>>>(p4, x, out);
}

// round 14
// speedup vs baseline: 1.0729x; 1.0240x over previous
#include <cuda_runtime.h>
#include <cuda_bf16.h>
#include <cuda_fp16.h>

#define L_SEQ   1024
#define DMODEL  2048
#define DINNER  4096
#define DSTATE  16
#define DTRANK  128
#define XPC     (DTRANK + 2 * DSTATE)   // 160
#define XPCP    256                     // padded GEMM2 N
#define TWOI    (2 * DINNER)
#define NCH     16              // scan chunks
#define CL      (L_SEQ / NCH)   // 64

// scratch (no allocation allowed)
__device__ __align__(16) __half g_xnc[L_SEQ * DMODEL];
__device__ __align__(16) __half g_w1c[TWOI * DMODEL];
__device__ __align__(16) __half g_uh[L_SEQ * DINNER];
__device__ __align__(16) __half g_wxph[XPCP * DINNER];
__device__ __align__(16) __half g_dtrh[L_SEQ * DTRANK];
__device__ __align__(16) __half g_wdth[DINNER * DTRANK];
__device__ __align__(16) __half g_deltah[L_SEQ * DINNER];
__device__ __align__(16) __half g_yc[L_SEQ * DINNER];
__device__ __align__(16) __half g_w4c[DMODEL * DINNER];
__device__ float g_xz[L_SEQ * TWOI];
__device__ float g_xdbc[L_SEQ * XPC];
#define G2_Z 8
__device__ float g_p2[G2_Z * L_SEQ * XPCP];
#define G4_Z 2
__device__ float g_p4[G4_Z * L_SEQ * DMODEL];
__device__ __align__(16) float g_hloc[NCH * DINNER * DSTATE];
__device__ __align__(16) float g_hin[NCH * DINNER * DSTATE];
__device__ float g_S[NCH * DINNER];

// ---------------- helpers ----------------
__device__ __forceinline__ unsigned smem_u32(const void* p) {
    unsigned a;
    asm("{ .reg .u64 t; cvta.to.shared.u64 t, %1; cvt.u32.u64 %0, t; }" : "=r"(a) : "l"(p));
    return a;
}
__device__ __forceinline__ void cpasync16(unsigned dst, const void* src) {
    asm volatile("cp.async.cg.shared.global [%0], [%1], 16;" :: "r"(dst), "l"(src) : "memory");
}
#define CP_COMMIT() asm volatile("cp.async.commit_group;" ::: "memory")
#define CP_WAIT1()  asm volatile("cp.async.wait_group 1;" ::: "memory")
__device__ __forceinline__ void ldsm_x4(unsigned& r0, unsigned& r1, unsigned& r2,
                                        unsigned& r3, unsigned addr) {
    asm volatile("ldmatrix.sync.aligned.m8n8.x4.shared.b16 {%0,%1,%2,%3}, [%4];"
                 : "=r"(r0), "=r"(r1), "=r"(r2), "=r"(r3) : "r"(addr));
}
__device__ __forceinline__ void mma16816(float* c, const unsigned* a, const unsigned* b) {
    asm volatile("mma.sync.aligned.m16n8k16.row.col.f32.f16.f16.f32 "
                 "{%0,%1,%2,%3}, {%4,%5,%6,%7}, {%8,%9}, {%0,%1,%2,%3};"
                 : "+f"(c[0]), "+f"(c[1]), "+f"(c[2]), "+f"(c[3])
                 : "r"(a[0]), "r"(a[1]), "r"(a[2]), "r"(a[3]), "r"(b[0]), "r"(b[1]));
}
// build p[n] = r^(n+1) for n=0..15 from r
__device__ __forceinline__ void pow_tree(float r, float* p) {
    p[0] = r; p[1] = r * r; p[2] = p[1] * r; p[3] = p[1] * p[1];
    const float r4 = p[3], r8 = r4 * r4, r12 = r8 * r4;
    #pragma unroll
    for (int j = 0; j < 4; j++) {
        p[4 + j] = p[j] * r4; p[8 + j] = p[j] * r8; p[12 + j] = p[j] * r12;
    }
}

// ------- weight transpose + convert: W[K,Nreal] fp32 -> Wc[Npad,K] fp16 -------
__global__ __launch_bounds__(256) void wconv_kernel(
    const float* __restrict__ W, __half* __restrict__ Wc, int K, int Nreal) {
    __shared__ float sW[32][33];
    const int n0 = blockIdx.x * 32, k0 = blockIdx.y * 32;
    const int c = threadIdx.x & 31, r = threadIdx.x >> 5;
    #pragma unroll
    for (int i = 0; i < 32; i += 8)
        sW[r + i][c] = (n0 + c < Nreal) ? W[(long)(k0 + r + i) * Nreal + n0 + c] : 0.f;
    __syncthreads();
    #pragma unroll
    for (int i = 0; i < 32; i += 8) {
        const int n = r + i;
        Wc[(long)(n0 + n) * K + k0 + c] = __float2half(sW[c][n]);
    }
}

// ---------------- RMSNorm -> xnc fp16 ----------------
__global__ __launch_bounds__(256) void rmsnorm_kernel(
    const float* __restrict__ x, const float* __restrict__ w,
    __half* __restrict__ xnc) {
    const int row = blockIdx.x;
    const float* xr = x + row * DMODEL;
    float s = 0.f;
    #pragma unroll
    for (int i = threadIdx.x; i < DMODEL; i += 256) {
        float v = xr[i];
        s += v * v;
    }
    #pragma unroll
    for (int o = 16; o > 0; o >>= 1) s += __shfl_xor_sync(0xffffffffu, s, o);
    __shared__ float red[8];
    __shared__ float rs_sh;
    if ((threadIdx.x & 31) == 0) red[threadIdx.x >> 5] = s;
    __syncthreads();
    if (threadIdx.x == 0) {
        float t = 0.f;
        #pragma unroll
        for (int i = 0; i < 8; i++) t += red[i];
        rs_sh = rsqrtf(t * (1.0f / DMODEL) + 1e-5f);
    }
    __syncthreads();
    const float rs = rs_sh;
    __half* dst = xnc + (long)row * DMODEL;
    #pragma unroll
    for (int i = threadIdx.x; i < DMODEL; i += 256)
        dst[i] = __float2half(xr[i] * rs * w[i]);
}

// ---------------- HMMA fp16 GEMM (R11 core: 128x128 CTA, 8 warps 32x64) --------
// EPI 0: fp32 store. EPI 1: softplus(acc + bias[col]) stored as fp16.
#define MM_S 3
#define MM_OPBYTES (128 * 40 * 2)          // 10240
#define MM_STAGEB (2 * MM_OPBYTES)         // 20480
#define MM_SMEM (MM_S * MM_STAGEB)         // 61440

template <int EPI>
__global__ __launch_bounds__(256, 2) void gemm_mma_kernel(
    const __half* __restrict__ A, const __half* __restrict__ B,
    float* __restrict__ C, int ldk, int ktiles, int Ntot, long zstride,
    const float* __restrict__ bias) {
    extern __shared__ char smraw[];
    const unsigned sb = smem_u32(smraw);
    const int tid = threadIdx.x;
    const int wid = tid >> 5, lane = tid & 31;
    const int m0 = blockIdx.x * 128, n0 = blockIdx.y * 128;
    const long kz = (long)blockIdx.z * ktiles * 32;

    const int lrow = tid >> 2;
    const int lch = tid & 3;
    const __half* Ag = A + (long)(m0 + lrow) * ldk + kz + lch * 8;
    const __half* Bg = B + (long)(n0 + lrow) * ldk + kz + lch * 8;
    const long half64 = 64L * ldk;
    const unsigned soff = lrow * 80 + lch * 16;

    float acc[2][8][4];
    #pragma unroll
    for (int i = 0; i < 2; i++)
        #pragma unroll
        for (int j = 0; j < 8; j++)
            #pragma unroll
            for (int q = 0; q < 4; q++) acc[i][j][q] = 0.f;

    #pragma unroll
    for (int s = 0; s < MM_S - 1; s++) {
        const unsigned st = sb + s * MM_STAGEB;
        const long ko = (long)s * 32;
        cpasync16(st + soff, Ag + ko);
        cpasync16(st + soff + 64 * 80, Ag + half64 + ko);
        cpasync16(st + MM_OPBYTES + soff, Bg + ko);
        cpasync16(st + MM_OPBYTES + soff + 64 * 80, Bg + half64 + ko);
        CP_COMMIT();
    }

    const int wm = (wid & 3) * 32;
    const int wn = (wid >> 2) * 64;
    const int lq = lane & 15;
    const int lh = (lane >> 4) * 16;

    int stage = 0, pstage = MM_S - 1;
    for (int kt = 0; kt < ktiles; kt++) {
        CP_WAIT1();
        __syncthreads();
        {
            const int pf = kt + MM_S - 1;
            if (pf < ktiles) {
                const unsigned st = sb + pstage * MM_STAGEB;
                const long ko = (long)pf * 32;
                cpasync16(st + soff, Ag + ko);
                cpasync16(st + soff + 64 * 80, Ag + half64 + ko);
                cpasync16(st + MM_OPBYTES + soff, Bg + ko);
                cpasync16(st + MM_OPBYTES + soff + 64 * 80, Bg + half64 + ko);
            }
            CP_COMMIT();
            pstage = (pstage + 1 == MM_S) ? 0 : pstage + 1;
        }
        const unsigned sa = sb + stage * MM_STAGEB;
        const unsigned sbB = sa + MM_OPBYTES;
        stage = (stage + 1 == MM_S) ? 0 : stage + 1;
        #pragma unroll
        for (int ks = 0; ks < 2; ks++) {
            const int kc = ks * 32;
            unsigned af[2][4];
            #pragma unroll
            for (int mi = 0; mi < 2; mi++)
                ldsm_x4(af[mi][0], af[mi][1], af[mi][2], af[mi][3],
                        sa + (wm + mi * 16 + lq) * 80 + kc + lh);
            unsigned bf[8][2];
            #pragma unroll
            for (int nj = 0; nj < 4; nj++) {
                unsigned r0, r1, r2, r3;
                ldsm_x4(r0, r1, r2, r3, sbB + (wn + nj * 16 + lq) * 80 + kc + lh);
                bf[2 * nj][0] = r0; bf[2 * nj][1] = r2;
                bf[2 * nj + 1][0] = r1; bf[2 * nj + 1][1] = r3;
            }
            #pragma unroll
            for (int mi = 0; mi < 2; mi++)
                #pragma unroll
                for (int nt = 0; nt < 8; nt++)
                    mma16816(acc[mi][nt], af[mi], bf[nt]);
        }
    }

    const int g = lane >> 2, t4 = lane & 3;
    if (EPI == 0) {
        float* Cb = C + (long)blockIdx.z * zstride;
        #pragma unroll
        for (int mi = 0; mi < 2; mi++) {
            const int r0 = m0 + wm + mi * 16 + g;
            #pragma unroll
            for (int nt = 0; nt < 8; nt++) {
                const int c0 = n0 + wn + nt * 8 + t4 * 2;
                *(float2*)&Cb[(long)r0 * Ntot + c0] =
                    make_float2(acc[mi][nt][0], acc[mi][nt][1]);
                *(float2*)&Cb[(long)(r0 + 8) * Ntot + c0] =
                    make_float2(acc[mi][nt][2], acc[mi][nt][3]);
            }
        }
    } else {
        __half* Ch = (__half*)C;
        #pragma unroll
        for (int mi = 0; mi < 2; mi++) {
            const int r0 = m0 + wm + mi * 16 + g;
            #pragma unroll
            for (int nt = 0; nt < 8; nt++) {
                const int c0 = n0 + wn + nt * 8 + t4 * 2;
                float v0 = acc[mi][nt][0] + bias[c0];
                float v1 = acc[mi][nt][1] + bias[c0 + 1];
                float v2 = acc[mi][nt][2] + bias[c0];
                float v3 = acc[mi][nt][3] + bias[c0 + 1];
                v0 = (v0 > 20.f) ? v0 : log1pf(__expf(v0));
                v1 = (v1 > 20.f) ? v1 : log1pf(__expf(v1));
                v2 = (v2 > 20.f) ? v2 : log1pf(__expf(v2));
                v3 = (v3 > 20.f) ? v3 : log1pf(__expf(v3));
                *(__half2*)&Ch[(long)r0 * Ntot + c0] = __floats2half2_rn(v0, v1);
                *(__half2*)&Ch[(long)(r0 + 8) * Ntot + c0] = __floats2half2_rn(v2, v3);
            }
        }
    }
}

// ---------------- reducers ----------------
__global__ __launch_bounds__(256) void reduce4_kernel(
    const float* __restrict__ p, const float* __restrict__ x, float* __restrict__ out) {
    const int idx = blockIdx.x * 256 + threadIdx.x;
    if (idx >= L_SEQ * DMODEL) return;
    const long off = (long)L_SEQ * DMODEL;
    out[idx] = x[idx] + (p[idx] + p[idx + off]);
}

__global__ __launch_bounds__(256) void reduce2_kernel(
    const float* __restrict__ p, float* __restrict__ xdbc,
    __half* __restrict__ dtrh) {
    const int idx = blockIdx.x * 256 + threadIdx.x;
    if (idx >= L_SEQ * XPCP) return;
    const long off = (long)L_SEQ * XPCP;
    float s = 0.f;
    #pragma unroll
    for (int z = 0; z < G2_Z; z++) s += p[idx + z * off];
    const int l = idx >> 8;
    const int col = idx & (XPCP - 1);
    if (col < XPC) xdbc[(long)l * XPC + col] = s;
    if (col < DTRANK) dtrh[(long)l * DTRANK + col] = __float2half(s);
}

// ---------------- depthwise causal conv + SiLU -> uh fp16 ----------------
__global__ __launch_bounds__(256) void conv_silu_kernel(
    const float* __restrict__ xz, const float* __restrict__ cw,
    const float* __restrict__ cb, __half* __restrict__ uh) {
    const int idx = blockIdx.x * 256 + threadIdx.x;
    if (idx >= L_SEQ * DINNER) return;
    const int l = idx >> 12, d = idx & (DINNER - 1);
    float acc = cb[d];
    #pragma unroll
    for (int j = 0; j < 4; j++) {
        const int ll = l - 3 + j;
        if (ll >= 0) acc += xz[(long)ll * TWOI + d] * cw[j * DINNER + d];
    }
    const float v = acc / (1.f + __expf(-acc));
    uh[idx] = __float2half(v);
}

// ---------------- chunked parallel scan ----------------
__global__ __launch_bounds__(128) void scan_part1(
    const __half* __restrict__ delta, const __half* __restrict__ uh,
    const float* __restrict__ xdbc, const float* __restrict__ A_log,
    float* __restrict__ hloc, float* __restrict__ S) {
    const int c = blockIdx.x;
    const int d = blockIdx.y * 128 + threadIdx.x;
    const int tid = threadIdx.x;
    const int l0 = c * CL;
    __shared__ float sB[CL][DSTATE];
    for (int t = tid; t < CL * DSTATE; t += 128) {
        const int i = t >> 4, n = t & 15;
        sB[i][n] = xdbc[(long)(l0 + i) * XPC + DTRANK + n];
    }
    float a[DSTATE];
    #pragma unroll
    for (int n = 0; n < DSTATE; n++) a[n] = -__expf(A_log[d * DSTATE + n]);
    const float a0 = a[0];
    bool pat = true;
    #pragma unroll
    for (int n = 1; n < DSTATE; n++) {
        const float e = a0 * (float)(n + 1);
        pat = pat && (fabsf(a[n] - e) <= 1e-4f * fabsf(e) + 1e-6f);
    }
    __syncthreads();
    float h[DSTATE];
    #pragma unroll
    for (int n = 0; n < DSTATE; n++) h[n] = 0.f;
    float Ss = 0.f;
    #pragma unroll 4
    for (int i = 0; i < CL; i++) {
        const int l = l0 + i;
        const float dl = __half2float(delta[(long)l * DINNER + d]);
        const float dbu = dl * __half2float(uh[(long)l * DINNER + d]);
        Ss += dl;
        if (pat) {
            float p[DSTATE];
            pow_tree(__expf(dl * a0), p);
            #pragma unroll
            for (int n = 0; n < DSTATE; n++) h[n] = h[n] * p[n] + dbu * sB[i][n];
        } else {
            #pragma unroll
            for (int n = 0; n < DSTATE; n++)
                h[n] = h[n] * __expf(dl * a[n]) + dbu * sB[i][n];
        }
    }
    float4* dst = (float4*)(hloc + ((long)c * DINNER + d) * DSTATE);
    #pragma unroll
    for (int q = 0; q < 4; q++)
        dst[q] = make_float4(h[4 * q], h[4 * q + 1], h[4 * q + 2], h[4 * q + 3]);
    S[c * DINNER + d] = Ss;
}

__global__ __launch_bounds__(128) void scan_combine(
    const float* __restrict__ hloc, const float* __restrict__ S,
    const float* __restrict__ A_log, float* __restrict__ hin) {
    const int d = blockIdx.x * 128 + threadIdx.x;
    float a[DSTATE];
    #pragma unroll
    for (int n = 0; n < DSTATE; n++) a[n] = -__expf(A_log[d * DSTATE + n]);
    const float a0 = a[0];
    bool pat = true;
    #pragma unroll
    for (int n = 1; n < DSTATE; n++) {
        const float e = a0 * (float)(n + 1);
        pat = pat && (fabsf(a[n] - e) <= 1e-4f * fabsf(e) + 1e-6f);
    }
    float h[DSTATE];
    #pragma unroll
    for (int n = 0; n < DSTATE; n++) h[n] = 0.f;
    for (int c = 0; c < NCH; c++) {
        float4* dst = (float4*)(hin + ((long)c * DINNER + d) * DSTATE);
        #pragma unroll
        for (int q = 0; q < 4; q++)
            dst[q] = make_float4(h[4 * q], h[4 * q + 1], h[4 * q + 2], h[4 * q + 3]);
        const float Ss = S[c * DINNER + d];
        const float4* src = (const float4*)(hloc + ((long)c * DINNER + d) * DSTATE);
        float hl[DSTATE];
        #pragma unroll
        for (int q = 0; q < 4; q++) {
            float4 v = src[q];
            hl[4 * q] = v.x; hl[4 * q + 1] = v.y; hl[4 * q + 2] = v.z; hl[4 * q + 3] = v.w;
        }
        if (pat) {
            float p[DSTATE];
            pow_tree(__expf(Ss * a0), p);
            #pragma unroll
            for (int n = 0; n < DSTATE; n++) h[n] = h[n] * p[n] + hl[n];
        } else {
            #pragma unroll
            for (int n = 0; n < DSTATE; n++)
                h[n] = h[n] * __expf(Ss * a[n]) + hl[n];
        }
    }
}

__global__ __launch_bounds__(128) void scan_part2(
    const __half* __restrict__ delta, const __half* __restrict__ uh,
    const float* __restrict__ xdbc, const float* __restrict__ A_log,
    const float* __restrict__ Dp, const float* __restrict__ xz,
    const float* __restrict__ hin, __half* __restrict__ yc) {
    const int c = blockIdx.x;
    const int d = blockIdx.y * 128 + threadIdx.x;
    const int tid = threadIdx.x;
    const int l0 = c * CL;
    __shared__ float sB[CL][DSTATE];
    __shared__ float sC[CL][DSTATE];
    for (int t = tid; t < CL * DSTATE; t += 128) {
        const int i = t >> 4, n = t & 15;
        sB[i][n] = xdbc[(long)(l0 + i) * XPC + DTRANK + n];
        sC[i][n] = xdbc[(long)(l0 + i) * XPC + DTRANK + DSTATE + n];
    }
    float a[DSTATE];
    #pragma unroll
    for (int n = 0; n < DSTATE; n++) a[n] = -__expf(A_log[d * DSTATE + n]);
    const float a0 = a[0];
    bool pat = true;
    #pragma unroll
    for (int n = 1; n < DSTATE; n++) {
        const float e = a0 * (float)(n + 1);
        pat = pat && (fabsf(a[n] - e) <= 1e-4f * fabsf(e) + 1e-6f);
    }
    const float Dd = Dp[d];
    float h[DSTATE];
    {
        const float4* src = (const float4*)(hin + ((long)c * DINNER + d) * DSTATE);
        #pragma unroll
        for (int q = 0; q < 4; q++) {
            float4 v = src[q];
            h[4 * q] = v.x; h[4 * q + 1] = v.y; h[4 * q + 2] = v.z; h[4 * q + 3] = v.w;
        }
    }
    __syncthreads();
    #pragma unroll 4
    for (int i = 0; i < CL; i++) {
        const int l = l0 + i;
        const float dl = __half2float(delta[(long)l * DINNER + d]);
        const float uv = __half2float(uh[(long)l * DINNER + d]);
        const float dbu = dl * uv;
        if (pat) {
            float p[DSTATE];
            pow_tree(__expf(dl * a0), p);
            #pragma unroll
            for (int n = 0; n < DSTATE; n++) h[n] = h[n] * p[n] + dbu * sB[i][n];
        } else {
            #pragma unroll
            for (int n = 0; n < DSTATE; n++)
                h[n] = h[n] * __expf(dl * a[n]) + dbu * sB[i][n];
        }
        float y0 = 0.f, y1 = 0.f, y2 = 0.f, y3 = 0.f;
        #pragma unroll
        for (int n = 0; n < DSTATE; n += 4) {
            y0 += h[n] * sC[i][n]; y1 += h[n + 1] * sC[i][n + 1];
            y2 += h[n + 2] * sC[i][n + 2]; y3 += h[n + 3] * sC[i][n + 3];
        }
        const float res = xz[(long)l * TWOI + DINNER + d];
        const float val = ((y0 + y1) + (y2 + y3) + uv * Dd) * (res / (1.f + __expf(-res)));
        yc[(long)l * DINNER + d] = __float2half(val);
    }
}

// ---------------- launch ----------------
extern "C" void kernel_launch(void* const* d_in, const int* in_sizes, int n_in,
                              void* d_out, int out_size) {
    const float* x      = (const float*)d_in[0];
    const float* w_norm = (const float*)d_in[1];
    const float* W_in   = (const float*)d_in[2];
    const float* conv_w = (const float*)d_in[3];
    const float* conv_b = (const float*)d_in[4];
    const float* W_xp   = (const float*)d_in[5];
    const float* W_dt   = (const float*)d_in[6];
    const float* b_dt   = (const float*)d_in[7];
    const float* A_log  = (const float*)d_in[8];
    const float* Dp     = (const float*)d_in[9];
    const float* W_out  = (const float*)d_in[10];
    float* out = (float*)d_out;

    __half *xnc, *w1c, *uh, *wxph, *dtrh, *wdth, *deltah, *yc, *w4c;
    float *xz, *xdbc, *p2, *p4, *hloc, *hin, *S;
    cudaGetSymbolAddress((void**)&xnc, g_xnc);
    cudaGetSymbolAddress((void**)&w1c, g_w1c);
    cudaGetSymbolAddress((void**)&uh, g_uh);
    cudaGetSymbolAddress((void**)&wxph, g_wxph);
    cudaGetSymbolAddress((void**)&dtrh, g_dtrh);
    cudaGetSymbolAddress((void**)&wdth, g_wdth);
    cudaGetSymbolAddress((void**)&deltah, g_deltah);
    cudaGetSymbolAddress((void**)&yc, g_yc);
    cudaGetSymbolAddress((void**)&w4c, g_w4c);
    cudaGetSymbolAddress((void**)&xz, g_xz);
    cudaGetSymbolAddress((void**)&xdbc, g_xdbc);
    cudaGetSymbolAddress((void**)&p2, g_p2);
    cudaGetSymbolAddress((void**)&p4, g_p4);
    cudaGetSymbolAddress((void**)&hloc, g_hloc);
    cudaGetSymbolAddress((void**)&hin, g_hin);
    cudaGetSymbolAddress((void**)&S, g_S);

    cudaFuncSetAttribute(gemm_mma_kernel<0>,
                         cudaFuncAttributeMaxDynamicSharedMemorySize, MM_SMEM);
    cudaFuncSetAttribute(gemm_mma_kernel<1>,
                         cudaFuncAttributeMaxDynamicSharedMemorySize, MM_SMEM);

    // weight transpose + fp16 convert
    wconv_kernel<<<dim3(TWOI / 32, DMODEL / 32), 256>>>(W_in, w1c, DMODEL, TWOI);
    wconv_kernel<<<dim3(DMODEL / 32, DINNER / 32), 256>>>(W_out, w4c, DINNER, DMODEL);
    wconv_kernel<<<dim3(XPCP / 32, DINNER / 32), 256>>>(W_xp, wxph, DINNER, XPC);
    wconv_kernel<<<dim3(DINNER / 32, DTRANK / 32), 256>>>(W_dt, wdth, DTRANK, DINNER);

    rmsnorm_kernel<<<L_SEQ, 256>>>(x, w_norm, xnc);

    // GEMM1: xz = xn @ W_in  (fp16 HMMA, K=2048)
    gemm_mma_kernel<0><<<dim3(L_SEQ / 128, TWOI / 128, 1), 256, MM_SMEM>>>(
        xnc, w1c, xz, DMODEL, DMODEL / 32, TWOI, 0, nullptr);

    conv_silu_kernel<<<(L_SEQ * DINNER) / 256, 256>>>(xz, conv_w, conv_b, uh);

    // GEMM2: xdbc = u @ W_xp  (fp16 HMMA, N padded 256, split-K z=8)
    gemm_mma_kernel<0><<<dim3(L_SEQ / 128, XPCP / 128, G2_Z), 256, MM_SMEM>>>(
        uh, wxph, p2, DINNER, DINNER / 32 / G2_Z, XPCP, (long)L_SEQ * XPCP, nullptr);
    reduce2_kernel<<<(L_SEQ * XPCP + 255) / 256, 256>>>(p2, xdbc, dtrh);

    // GEMM3: delta = softplus(dt_r @ W_dt + b_dt) -> fp16  (HMMA, K=128)
    gemm_mma_kernel<1><<<dim3(L_SEQ / 128, DINNER / 128, 1), 256, MM_SMEM>>>(
        dtrh, wdth, (float*)deltah, DTRANK, DTRANK / 32, DINNER, 0, b_dt);

    // chunked scan (NCH=16)
    scan_part1<<<dim3(NCH, DINNER / 128), 128>>>(deltah, uh, xdbc, A_log, hloc, S);
    scan_combine<<<DINNER / 128, 128>>>(hloc, S, A_log, hin);
    scan_part2<<<dim3(NCH, DINNER / 128), 128>>>(deltah, uh, xdbc, A_log, Dp, xz, hin, yc);

    // GEMM4: p4[z] = (yz @ W_out) split-K z=2  (fp16 HMMA, K=4096)
    gemm_mma_kernel<0><<<dim3(L_SEQ / 128, DMODEL / 128, G4_Z), 256, MM_SMEM>>>(
        yc, w4c, p4, DINNER, DINNER / 32 / G4_Z, DMODEL, (long)L_SEQ * DMODEL, nullptr);

    reduce4_kernel<<<(L_SEQ * DMODEL + 255) / 256, 256>>>(p4, x, out);
}

// round 17
// speedup vs baseline: 1.0832x; 1.0096x over previous
#include <cuda_runtime.h>
#include <cuda_bf16.h>
#include <cuda_fp16.h>

#define L_SEQ   1024
#define DMODEL  2048
#define DINNER  4096
#define DSTATE  16
#define DTRANK  128
#define XPC     (DTRANK + 2 * DSTATE)   // 160
#define XPCP    256                     // padded GEMM2 N
#define TWOI    (2 * DINNER)
#define NCH     16              // scan chunks
#define CL      (L_SEQ / NCH)   // 64

// scratch (no allocation allowed)
__device__ __align__(16) __half g_xnc[L_SEQ * DMODEL];
__device__ __align__(16) __half g_w1c[TWOI * DMODEL];
__device__ __align__(16) __half g_xzh[L_SEQ * TWOI];
__device__ __align__(16) __half g_uh[L_SEQ * DINNER];
__device__ __align__(16) __half g_wxph[XPCP * DINNER];
__device__ __align__(16) __half g_dtrh[L_SEQ * DTRANK];
__device__ __align__(16) __half g_wdth[DINNER * DTRANK];
__device__ __align__(16) __half g_deltah[L_SEQ * DINNER];
__device__ __align__(16) __half g_yc[L_SEQ * DINNER];
__device__ __align__(16) __half g_w4c[DMODEL * DINNER];
__device__ float g_xdbc[L_SEQ * XPC];
#define G2_Z 8
__device__ float g_p2[G2_Z * L_SEQ * XPCP];
#define G4_Z 2
__device__ float g_p4[G4_Z * L_SEQ * DMODEL];
__device__ __align__(16) float g_hloc[NCH * DINNER * DSTATE];
__device__ __align__(16) float g_hin[NCH * DINNER * DSTATE];
__device__ float g_S[NCH * DINNER];

// ---------------- helpers ----------------
__device__ __forceinline__ unsigned smem_u32(const void* p) {
    unsigned a;
    asm("{ .reg .u64 t; cvta.to.shared.u64 t, %1; cvt.u32.u64 %0, t; }" : "=r"(a) : "l"(p));
    return a;
}
__device__ __forceinline__ void cpasync16(unsigned dst, const void* src) {
    asm volatile("cp.async.cg.shared.global [%0], [%1], 16;" :: "r"(dst), "l"(src) : "memory");
}
#define CP_COMMIT() asm volatile("cp.async.commit_group;" ::: "memory")
#define CP_WAIT1()  asm volatile("cp.async.wait_group 1;" ::: "memory")
__device__ __forceinline__ void ldsm_x4(unsigned& r0, unsigned& r1, unsigned& r2,
                                        unsigned& r3, unsigned addr) {
    asm volatile("ldmatrix.sync.aligned.m8n8.x4.shared.b16 {%0,%1,%2,%3}, [%4];"
                 : "=r"(r0), "=r"(r1), "=r"(r2), "=r"(r3) : "r"(addr));
}
__device__ __forceinline__ void mma16816(float* c, const unsigned* a, const unsigned* b) {
    asm volatile("mma.sync.aligned.m16n8k16.row.col.f32.f16.f16.f32 "
                 "{%0,%1,%2,%3}, {%4,%5,%6,%7}, {%8,%9}, {%0,%1,%2,%3};"
                 : "+f"(c[0]), "+f"(c[1]), "+f"(c[2]), "+f"(c[3])
                 : "r"(a[0]), "r"(a[1]), "r"(a[2]), "r"(a[3]), "r"(b[0]), "r"(b[1]));
}
// build p[n] = r^(n+1) for n=0..15 from r
__device__ __forceinline__ void pow_tree(float r, float* p) {
    p[0] = r; p[1] = r * r; p[2] = p[1] * r; p[3] = p[1] * p[1];
    const float r4 = p[3], r8 = r4 * r4, r12 = r8 * r4;
    #pragma unroll
    for (int j = 0; j < 4; j++) {
        p[4 + j] = p[j] * r4; p[8 + j] = p[j] * r8; p[12 + j] = p[j] * r12;
    }
}

// ------- weight transpose + convert: W[K,Nreal] fp32 -> Wc[Npad,K] fp16 -------
// 64x64 tile, float4 loads, uint4 (8x half) stores. K % 64 == 0, Npad % 64 == 0.
// smem stride 68 (multiple of 4) keeps the float4 STS 16B-aligned.
__global__ __launch_bounds__(256) void wconv_kernel(
    const float* __restrict__ W, __half* __restrict__ Wc, int K, int Nreal) {
    __shared__ float sW[64][68];
    const int n0 = blockIdx.x * 64, k0 = blockIdx.y * 64;
    const int t = threadIdx.x;
    const int lc = (t & 15) * 4;   // n within tile
    const int lr = t >> 4;         // 0..15 (k row base)
    #pragma unroll
    for (int i = 0; i < 4; i++) {
        const int row = lr + i * 16;
        const int gn = n0 + lc;
        if (gn + 3 < Nreal) {
            *(float4*)&sW[row][lc] =
                *(const float4*)&W[(long)(k0 + row) * Nreal + gn];
        } else {
            #pragma unroll
            for (int j = 0; j < 4; j++)
                sW[row][lc + j] =
                    (gn + j < Nreal) ? W[(long)(k0 + row) * Nreal + gn + j] : 0.f;
        }
    }
    __syncthreads();
    const int n = t >> 2;
    #pragma unroll
    for (int g = 0; g < 2; g++) {
        const int kk = (t & 3) * 8 + g * 32;
        __align__(16) __half hbuf[8];
        #pragma unroll
        for (int j = 0; j < 8; j++) hbuf[j] = __float2half(sW[kk + j][n]);
        *(uint4*)&Wc[(long)(n0 + n) * K + k0 + kk] = *(uint4*)hbuf;
    }
}

// ---------------- RMSNorm -> xnc fp16 ----------------
__global__ __launch_bounds__(256) void rmsnorm_kernel(
    const float* __restrict__ x, const float* __restrict__ w,
    __half* __restrict__ xnc) {
    const int row = blockIdx.x;
    const float* xr = x + row * DMODEL;
    float s = 0.f;
    #pragma unroll
    for (int i = threadIdx.x; i < DMODEL; i += 256) {
        float v = xr[i];
        s += v * v;
    }
    #pragma unroll
    for (int o = 16; o > 0; o >>= 1) s += __shfl_xor_sync(0xffffffffu, s, o);
    __shared__ float red[8];
    __shared__ float rs_sh;
    if ((threadIdx.x & 31) == 0) red[threadIdx.x >> 5] = s;
    __syncthreads();
    if (threadIdx.x == 0) {
        float t = 0.f;
        #pragma unroll
        for (int i = 0; i < 8; i++) t += red[i];
        rs_sh = rsqrtf(t * (1.0f / DMODEL) + 1e-5f);
    }
    __syncthreads();
    const float rs = rs_sh;
    __half* dst = xnc + (long)row * DMODEL;
    #pragma unroll
    for (int i = threadIdx.x; i < DMODEL; i += 256)
        dst[i] = __float2half(xr[i] * rs * w[i]);
}

// ---------------- HMMA fp16 GEMM (128x128 CTA, 8 warps 32x64, 3-stage) --------
// EPI 0: fp32 store. EPI 1: softplus(acc + bias) -> fp16. EPI 2: plain fp16.
#define MM_S 3
#define MM_OPBYTES (128 * 40 * 2)          // 10240
#define MM_STAGEB (2 * MM_OPBYTES)         // 20480
#define MM_SMEM (MM_S * MM_STAGEB)         // 61440

template <int EPI>
__global__ __launch_bounds__(256, 2) void gemm_mma_kernel(
    const __half* __restrict__ A, const __half* __restrict__ B,
    float* __restrict__ C, int ldk, int ktiles, int Ntot, long zstride,
    const float* __restrict__ bias) {
    extern __shared__ char smraw[];
    const unsigned sb = smem_u32(smraw);
    const int tid = threadIdx.x;
    const int wid = tid >> 5, lane = tid & 31;
    const int m0 = blockIdx.x * 128, n0 = blockIdx.y * 128;
    const long kz = (long)blockIdx.z * ktiles * 32;

    const int lrow = tid >> 2;
    const int lch = tid & 3;
    const __half* Ag = A + (long)(m0 + lrow) * ldk + kz + lch * 8;
    const __half* Bg = B + (long)(n0 + lrow) * ldk + kz + lch * 8;
    const long half64 = 64L * ldk;
    const unsigned soff = lrow * 80 + lch * 16;

    float acc[2][8][4];
    #pragma unroll
    for (int i = 0; i < 2; i++)
        #pragma unroll
        for (int j = 0; j < 8; j++)
            #pragma unroll
            for (int q = 0; q < 4; q++) acc[i][j][q] = 0.f;

    #pragma unroll
    for (int s = 0; s < MM_S - 1; s++) {
        const unsigned st = sb + s * MM_STAGEB;
        const long ko = (long)s * 32;
        cpasync16(st + soff, Ag + ko);
        cpasync16(st + soff + 64 * 80, Ag + half64 + ko);
        cpasync16(st + MM_OPBYTES + soff, Bg + ko);
        cpasync16(st + MM_OPBYTES + soff + 64 * 80, Bg + half64 + ko);
        CP_COMMIT();
    }

    const int wm = (wid & 3) * 32;
    const int wn = (wid >> 2) * 64;
    const int lq = lane & 15;
    const int lh = (lane >> 4) * 16;

    int stage = 0, pstage = MM_S - 1;
    for (int kt = 0; kt < ktiles; kt++) {
        CP_WAIT1();
        __syncthreads();
        {
            const int pf = kt + MM_S - 1;
            if (pf < ktiles) {
                const unsigned st = sb + pstage * MM_STAGEB;
                const long ko = (long)pf * 32;
                cpasync16(st + soff, Ag + ko);
                cpasync16(st + soff + 64 * 80, Ag + half64 + ko);
                cpasync16(st + MM_OPBYTES + soff, Bg + ko);
                cpasync16(st + MM_OPBYTES + soff + 64 * 80, Bg + half64 + ko);
            }
            CP_COMMIT();
            pstage = (pstage + 1 == MM_S) ? 0 : pstage + 1;
        }
        const unsigned sa = sb + stage * MM_STAGEB;
        const unsigned sbB = sa + MM_OPBYTES;
        stage = (stage + 1 == MM_S) ? 0 : stage + 1;
        #pragma unroll
        for (int ks = 0; ks < 2; ks++) {
            const int kc = ks * 32;
            unsigned af[2][4];
            #pragma unroll
            for (int mi = 0; mi < 2; mi++)
                ldsm_x4(af[mi][0], af[mi][1], af[mi][2], af[mi][3],
                        sa + (wm + mi * 16 + lq) * 80 + kc + lh);
            unsigned bf[8][2];
            #pragma unroll
            for (int nj = 0; nj < 4; nj++) {
                unsigned r0, r1, r2, r3;
                ldsm_x4(r0, r1, r2, r3, sbB + (wn + nj * 16 + lq) * 80 + kc + lh);
                bf[2 * nj][0] = r0; bf[2 * nj][1] = r2;
                bf[2 * nj + 1][0] = r1; bf[2 * nj + 1][1] = r3;
            }
            #pragma unroll
            for (int mi = 0; mi < 2; mi++)
                #pragma unroll
                for (int nt = 0; nt < 8; nt++)
                    mma16816(acc[mi][nt], af[mi], bf[nt]);
        }
    }

    const int g = lane >> 2, t4 = lane & 3;
    if (EPI == 0) {
        float* Cb = C + (long)blockIdx.z * zstride;
        #pragma unroll
        for (int mi = 0; mi < 2; mi++) {
            const int r0 = m0 + wm + mi * 16 + g;
            #pragma unroll
            for (int nt = 0; nt < 8; nt++) {
                const int c0 = n0 + wn + nt * 8 + t4 * 2;
                *(float2*)&Cb[(long)r0 * Ntot + c0] =
                    make_float2(acc[mi][nt][0], acc[mi][nt][1]);
                *(float2*)&Cb[(long)(r0 + 8) * Ntot + c0] =
                    make_float2(acc[mi][nt][2], acc[mi][nt][3]);
            }
        }
    } else if (EPI == 1) {
        __half* Ch = (__half*)C;
        #pragma unroll
        for (int mi = 0; mi < 2; mi++) {
            const int r0 = m0 + wm + mi * 16 + g;
            #pragma unroll
            for (int nt = 0; nt < 8; nt++) {
                const int c0 = n0 + wn + nt * 8 + t4 * 2;
                float v0 = acc[mi][nt][0] + bias[c0];
                float v1 = acc[mi][nt][1] + bias[c0 + 1];
                float v2 = acc[mi][nt][2] + bias[c0];
                float v3 = acc[mi][nt][3] + bias[c0 + 1];
                v0 = (v0 > 20.f) ? v0 : log1pf(__expf(v0));
                v1 = (v1 > 20.f) ? v1 : log1pf(__expf(v1));
                v2 = (v2 > 20.f) ? v2 : log1pf(__expf(v2));
                v3 = (v3 > 20.f) ? v3 : log1pf(__expf(v3));
                *(__half2*)&Ch[(long)r0 * Ntot + c0] = __floats2half2_rn(v0, v1);
                *(__half2*)&Ch[(long)(r0 + 8) * Ntot + c0] = __floats2half2_rn(v2, v3);
            }
        }
    } else {
        __half* Ch = (__half*)C;
        #pragma unroll
        for (int mi = 0; mi < 2; mi++) {
            const int r0 = m0 + wm + mi * 16 + g;
            #pragma unroll
            for (int nt = 0; nt < 8; nt++) {
                const int c0 = n0 + wn + nt * 8 + t4 * 2;
                *(__half2*)&Ch[(long)r0 * Ntot + c0] =
                    __floats2half2_rn(acc[mi][nt][0], acc[mi][nt][1]);
                *(__half2*)&Ch[(long)(r0 + 8) * Ntot + c0] =
                    __floats2half2_rn(acc[mi][nt][2], acc[mi][nt][3]);
            }
        }
    }
}

// ---------------- reducers ----------------
__global__ __launch_bounds__(256) void reduce4_kernel(
    const float* __restrict__ p, const float* __restrict__ x, float* __restrict__ out) {
    const int idx = blockIdx.x * 256 + threadIdx.x;
    if (idx >= L_SEQ * DMODEL) return;
    const long off = (long)L_SEQ * DMODEL;
    out[idx] = x[idx] + (p[idx] + p[idx + off]);
}

__global__ __launch_bounds__(256) void reduce2_kernel(
    const float* __restrict__ p, float* __restrict__ xdbc,
    __half* __restrict__ dtrh) {
    const int idx = blockIdx.x * 256 + threadIdx.x;
    if (idx >= L_SEQ * XPCP) return;
    const long off = (long)L_SEQ * XPCP;
    float s = 0.f;
    #pragma unroll
    for (int z = 0; z < G2_Z; z++) s += p[idx + z * off];
    const int l = idx >> 8;
    const int col = idx & (XPCP - 1);
    if (col < XPC) xdbc[(long)l * XPC + col] = s;
    if (col < DTRANK) dtrh[(long)l * DTRANK + col] = __float2half(s);
}

// ---------------- depthwise causal conv + SiLU (fp16 in/out) ----------------
__global__ __launch_bounds__(256) void conv_silu_kernel(
    const __half* __restrict__ xz, const float* __restrict__ cw,
    const float* __restrict__ cb, __half* __restrict__ uh) {
    const int idx = blockIdx.x * 256 + threadIdx.x;
    if (idx >= L_SEQ * DINNER) return;
    const int l = idx >> 12, d = idx & (DINNER - 1);
    float acc = cb[d];
    #pragma unroll
    for (int j = 0; j < 4; j++) {
        const int ll = l - 3 + j;
        if (ll >= 0)
            acc += __half2float(xz[(long)ll * TWOI + d]) * cw[j * DINNER + d];
    }
    const float v = acc / (1.f + __expf(-acc));
    uh[idx] = __float2half(v);
}

// ---------------- chunked parallel scan ----------------
__global__ __launch_bounds__(128) void scan_part1(
    const __half* __restrict__ delta, const __half* __restrict__ uh,
    const float* __restrict__ xdbc, const float* __restrict__ A_log,
    float* __restrict__ hloc, float* __restrict__ S) {
    const int c = blockIdx.x;
    const int d = blockIdx.y * 128 + threadIdx.x;
    const int tid = threadIdx.x;
    const int l0 = c * CL;
    __shared__ float sB[CL][DSTATE];
    for (int t = tid; t < CL * DSTATE; t += 128) {
        const int i = t >> 4, n = t & 15;
        sB[i][n] = xdbc[(long)(l0 + i) * XPC + DTRANK + n];
    }
    float a[DSTATE];
    #pragma unroll
    for (int n = 0; n < DSTATE; n++) a[n] = -__expf(A_log[d * DSTATE + n]);
    const float a0 = a[0];
    bool pat = true;
    #pragma unroll
    for (int n = 1; n < DSTATE; n++) {
        const float e = a0 * (float)(n + 1);
        pat = pat && (fabsf(a[n] - e) <= 1e-4f * fabsf(e) + 1e-6f);
    }
    __syncthreads();
    float h[DSTATE];
    #pragma unroll
    for (int n = 0; n < DSTATE; n++) h[n] = 0.f;
    float Ss = 0.f;
    #pragma unroll 4
    for (int i = 0; i < CL; i++) {
        const int l = l0 + i;
        const float dl = __half2float(delta[(long)l * DINNER + d]);
        const float dbu = dl * __half2float(uh[(long)l * DINNER + d]);
        Ss += dl;
        if (pat) {
            float p[DSTATE];
            pow_tree(__expf(dl * a0), p);
            #pragma unroll
            for (int n = 0; n < DSTATE; n++) h[n] = h[n] * p[n] + dbu * sB[i][n];
        } else {
            #pragma unroll
            for (int n = 0; n < DSTATE; n++)
                h[n] = h[n] * __expf(dl * a[n]) + dbu * sB[i][n];
        }
    }
    float4* dst = (float4*)(hloc + ((long)c * DINNER + d) * DSTATE);
    #pragma unroll
    for (int q = 0; q < 4; q++)
        dst[q] = make_float4(h[4 * q], h[4 * q + 1], h[4 * q + 2], h[4 * q + 3]);
    S[c * DINNER + d] = Ss;
}

__global__ __launch_bounds__(128) void scan_combine(
    const float* __restrict__ hloc, const float* __restrict__ S,
    const float* __restrict__ A_log, float* __restrict__ hin) {
    const int d = blockIdx.x * 128 + threadIdx.x;
    float a[DSTATE];
    #pragma unroll
    for (int n = 0; n < DSTATE; n++) a[n] = -__expf(A_log[d * DSTATE + n]);
    const float a0 = a[0];
    bool pat = true;
    #pragma unroll
    for (int n = 1; n < DSTATE; n++) {
        const float e = a0 * (float)(n + 1);
        pat = pat && (fabsf(a[n] - e) <= 1e-4f * fabsf(e) + 1e-6f);
    }
    float h[DSTATE];
    #pragma unroll
    for (int n = 0; n < DSTATE; n++) h[n] = 0.f;
    for (int c = 0; c < NCH; c++) {
        float4* dst = (float4*)(hin + ((long)c * DINNER + d) * DSTATE);
        #pragma unroll
        for (int q = 0; q < 4; q++)
            dst[q] = make_float4(h[4 * q], h[4 * q + 1], h[4 * q + 2], h[4 * q + 3]);
        const float Ss = S[c * DINNER + d];
        const float4* src = (const float4*)(hloc + ((long)c * DINNER + d) * DSTATE);
        float hl[DSTATE];
        #pragma unroll
        for (int q = 0; q < 4; q++) {
            float4 v = src[q];
            hl[4 * q] = v.x; hl[4 * q + 1] = v.y; hl[4 * q + 2] = v.z; hl[4 * q + 3] = v.w;
        }
        if (pat) {
            float p[DSTATE];
            pow_tree(__expf(Ss * a0), p);
            #pragma unroll
            for (int n = 0; n < DSTATE; n++) h[n] = h[n] * p[n] + hl[n];
        } else {
            #pragma unroll
            for (int n = 0; n < DSTATE; n++)
                h[n] = h[n] * __expf(Ss * a[n]) + hl[n];
        }
    }
}

__global__ __launch_bounds__(128) void scan_part2(
    const __half* __restrict__ delta, const __half* __restrict__ uh,
    const float* __restrict__ xdbc, const float* __restrict__ A_log,
    const float* __restrict__ Dp, const __half* __restrict__ xz,
    const float* __restrict__ hin, __half* __restrict__ yc) {
    const int c = blockIdx.x;
    const int d = blockIdx.y * 128 + threadIdx.x;
    const int tid = threadIdx.x;
    const int l0 = c * CL;
    __shared__ float sB[CL][DSTATE];
    __shared__ float sC[CL][DSTATE];
    for (int t = tid; t < CL * DSTATE; t += 128) {
        const int i = t >> 4, n = t & 15;
        sB[i][n] = xdbc[(long)(l0 + i) * XPC + DTRANK + n];
        sC[i][n] = xdbc[(long)(l0 + i) * XPC + DTRANK + DSTATE + n];
    }
    float a[DSTATE];
    #pragma unroll
    for (int n = 0; n < DSTATE; n++) a[n] = -__expf(A_log[d * DSTATE + n]);
    const float a0 = a[0];
    bool pat = true;
    #pragma unroll
    for (int n = 1; n < DSTATE; n++) {
        const float e = a0 * (float)(n + 1);
        pat = pat && (fabsf(a[n] - e) <= 1e-4f * fabsf(e) + 1e-6f);
    }
    const float Dd = Dp[d];
    float h[DSTATE];
    {
        const float4* src = (const float4*)(hin + ((long)c * DINNER + d) * DSTATE);
        #pragma unroll
        for (int q = 0; q < 4; q++) {
            float4 v = src[q];
            h[4 * q] = v.x; h[4 * q + 1] = v.y; h[4 * q + 2] = v.z; h[4 * q + 3] = v.w;
        }
    }
    __syncthreads();
    #pragma unroll 4
    for (int i = 0; i < CL; i++) {
        const int l = l0 + i;
        const float dl = __half2float(delta[(long)l * DINNER + d]);
        const float uv = __half2float(uh[(long)l * DINNER + d]);
        const float dbu = dl * uv;
        if (pat) {
            float p[DSTATE];
            pow_tree(__expf(dl * a0), p);
            #pragma unroll
            for (int n = 0; n < DSTATE; n++) h[n] = h[n] * p[n] + dbu * sB[i][n];
        } else {
            #pragma unroll
            for (int n = 0; n < DSTATE; n++)
                h[n] = h[n] * __expf(dl * a[n]) + dbu * sB[i][n];
        }
        float y0 = 0.f, y1 = 0.f, y2 = 0.f, y3 = 0.f;
        #pragma unroll
        for (int n = 0; n < DSTATE; n += 4) {
            y0 += h[n] * sC[i][n]; y1 += h[n + 1] * sC[i][n + 1];
            y2 += h[n + 2] * sC[i][n + 2]; y3 += h[n + 3] * sC[i][n + 3];
        }
        const float res = __half2float(xz[(long)l * TWOI + DINNER + d]);
        const float val = ((y0 + y1) + (y2 + y3) + uv * Dd) * (res / (1.f + __expf(-res)));
        yc[(long)l * DINNER + d] = __float2half(val);
    }
}

// ---------------- launch ----------------
extern "C" void kernel_launch(void* const* d_in, const int* in_sizes, int n_in,
                              void* d_out, int out_size) {
    const float* x      = (const float*)d_in[0];
    const float* w_norm = (const float*)d_in[1];
    const float* W_in   = (const float*)d_in[2];
    const float* conv_w = (const float*)d_in[3];
    const float* conv_b = (const float*)d_in[4];
    const float* W_xp   = (const float*)d_in[5];
    const float* W_dt   = (const float*)d_in[6];
    const float* b_dt   = (const float*)d_in[7];
    const float* A_log  = (const float*)d_in[8];
    const float* Dp     = (const float*)d_in[9];
    const float* W_out  = (const float*)d_in[10];
    float* out = (float*)d_out;

    __half *xnc, *w1c, *xzh, *uh, *wxph, *dtrh, *wdth, *deltah, *yc, *w4c;
    float *xdbc, *p2, *p4, *hloc, *hin, *S;
    cudaGetSymbolAddress((void**)&xnc, g_xnc);
    cudaGetSymbolAddress((void**)&w1c, g_w1c);
    cudaGetSymbolAddress((void**)&xzh, g_xzh);
    cudaGetSymbolAddress((void**)&uh, g_uh);
    cudaGetSymbolAddress((void**)&wxph, g_wxph);
    cudaGetSymbolAddress((void**)&dtrh, g_dtrh);
    cudaGetSymbolAddress((void**)&wdth, g_wdth);
    cudaGetSymbolAddress((void**)&deltah, g_deltah);
    cudaGetSymbolAddress((void**)&yc, g_yc);
    cudaGetSymbolAddress((void**)&w4c, g_w4c);
    cudaGetSymbolAddress((void**)&xdbc, g_xdbc);
    cudaGetSymbolAddress((void**)&p2, g_p2);
    cudaGetSymbolAddress((void**)&p4, g_p4);
    cudaGetSymbolAddress((void**)&hloc, g_hloc);
    cudaGetSymbolAddress((void**)&hin, g_hin);
    cudaGetSymbolAddress((void**)&S, g_S);

    cudaFuncSetAttribute(gemm_mma_kernel<0>,
                         cudaFuncAttributeMaxDynamicSharedMemorySize, MM_SMEM);
    cudaFuncSetAttribute(gemm_mma_kernel<1>,
                         cudaFuncAttributeMaxDynamicSharedMemorySize, MM_SMEM);
    cudaFuncSetAttribute(gemm_mma_kernel<2>,
                         cudaFuncAttributeMaxDynamicSharedMemorySize, MM_SMEM);

    // weight transpose + fp16 convert (64x64 tiles)
    wconv_kernel<<<dim3(TWOI / 64, DMODEL / 64), 256>>>(W_in, w1c, DMODEL, TWOI);
    wconv_kernel<<<dim3(DMODEL / 64, DINNER / 64), 256>>>(W_out, w4c, DINNER, DMODEL);
    wconv_kernel<<<dim3(XPCP / 64, DINNER / 64), 256>>>(W_xp, wxph, DINNER, XPC);
    wconv_kernel<<<dim3(DINNER / 64, DTRANK / 64), 256>>>(W_dt, wdth, DTRANK, DINNER);

    rmsnorm_kernel<<<L_SEQ, 256>>>(x, w_norm, xnc);

    // GEMM1: xz = xn @ W_in  (fp16 HMMA, K=2048) -> fp16 output
    gemm_mma_kernel<2><<<dim3(L_SEQ / 128, TWOI / 128, 1), 256, MM_SMEM>>>(
        xnc, w1c, (float*)xzh, DMODEL, DMODEL / 32, TWOI, 0, nullptr);

    conv_silu_kernel<<<(L_SEQ * DINNER) / 256, 256>>>(xzh, conv_w, conv_b, uh);

    // GEMM2: xdbc = u @ W_xp  (fp16 HMMA, N padded 256, split-K z=8)
    gemm_mma_kernel<0><<<dim3(L_SEQ / 128, XPCP / 128, G2_Z), 256, MM_SMEM>>>(
        uh, wxph, p2, DINNER, DINNER / 32 / G2_Z, XPCP, (long)L_SEQ * XPCP, nullptr);
    reduce2_kernel<<<(L_SEQ * XPCP + 255) / 256, 256>>>(p2, xdbc, dtrh);

    // GEMM3: delta = softplus(dt_r @ W_dt + b_dt) -> fp16  (HMMA, K=128)
    gemm_mma_kernel<1><<<dim3(L_SEQ / 128, DINNER / 128, 1), 256, MM_SMEM>>>(
        dtrh, wdth, (float*)deltah, DTRANK, DTRANK / 32, DINNER, 0, b_dt);

    // chunked scan (NCH=16)
    scan_part1<<<dim3(NCH, DINNER / 128), 128>>>(deltah, uh, xdbc, A_log, hloc, S);
    scan_combine<<<DINNER / 128, 128>>>(hloc, S, A_log, hin);
    scan_part2<<<dim3(NCH, DINNER / 128), 128>>>(deltah, uh, xdbc, A_log, Dp, xzh, hin, yc);

    // GEMM4: p4[z] = (yz @ W_out) split-K z=2  (fp16 HMMA, K=4096)
    gemm_mma_kernel<0><<<dim3(L_SEQ / 128, DMODEL / 128, G4_Z), 256, MM_SMEM>>>(
        yc, w4c, p4, DINNER, DINNER / 32 / G4_Z, DMODEL, (long)L_SEQ * DMODEL, nullptr);

    reduce4_kernel<<<(L_SEQ * DMODEL + 255) / 256, 256>>>(p4, x, out);
}